// round 9
// baseline (speedup 1.0000x reference)
#include <cuda_runtime.h>
#include <cuda_bf16.h>
#include <cstdint>

// ---------------- problem constants ----------------
#define T_TOK  32768
#define K_CODE 8192
#define D_DIM  128
#define NTILE2 32            // K_CODE / 256 column tiles
#define DECAY  0.1f
#define OMD    0.9f
#define EPSF   1e-5f

// output layout (all fp32, concatenated in reference return order)
static const size_t OFF_I    = (size_t)T_TOK * D_DIM;             // after quantized
static const size_t OFF_DIST = OFF_I + T_TOK;                     // after indices
static const size_t OFF_NE   = OFF_DIST + (size_t)T_TOK * K_CODE; // after dist
static const size_t OFF_NCS  = OFF_NE + (size_t)K_CODE * D_DIM;   // after new_embed
static const size_t OFF_NEA  = OFF_NCS + K_CODE;                  // after new_cluster_size

// ---------------- device scratch (no allocations allowed) ----------------
__device__ __align__(16) __nv_bfloat16 g_Abf[(size_t)T_TOK * D_DIM];   // 8 MB
__device__ __align__(16) __nv_bfloat16 g_Bbf[(size_t)K_CODE * D_DIM];  // 2 MB
__device__ float g_x2[T_TOK];
__device__ float g_e2[K_CODE];
__device__ unsigned long long g_tbest[(size_t)T_TOK * NTILE2];         // 8 MB (fully overwritten)
__device__ float g_cs[K_CODE];
__device__ __align__(16) float g_es[(size_t)K_CODE * D_DIM];           // 4 MB
__device__ float g_S;

__device__ __forceinline__ uint32_t smem_u32(const void* p) {
    return (uint32_t)__cvta_generic_to_shared(p);
}

// ---------------- prep kernels (warp-per-row, float4) ----------------
__global__ void __launch_bounds__(256) prep_x_kernel(const float* __restrict__ x) {
    int t = blockIdx.x * 8 + (threadIdx.x >> 5);     // token
    int lane = threadIdx.x & 31;
    float4 v = *(const float4*)(x + (size_t)t * D_DIM + lane * 4);
    __nv_bfloat162 p0, p1;
    p0.x = __float2bfloat16(v.x); p0.y = __float2bfloat16(v.y);
    p1.x = __float2bfloat16(v.z); p1.y = __float2bfloat16(v.w);
    __nv_bfloat162* dst = (__nv_bfloat162*)(g_Abf + (size_t)t * D_DIM + lane * 4);
    dst[0] = p0; dst[1] = p1;
    float s = v.x * v.x + v.y * v.y + v.z * v.z + v.w * v.w;
    for (int o = 16; o; o >>= 1) s += __shfl_xor_sync(0xffffffffu, s, o);
    if (lane == 0) g_x2[t] = s;
}

__global__ void __launch_bounds__(256) prep_e_kernel(const float* __restrict__ embed) {
    int k = blockIdx.x * 8 + (threadIdx.x >> 5);     // code
    int lane = threadIdx.x & 31;
    float4 v = *(const float4*)(embed + (size_t)k * D_DIM + lane * 4);
    __nv_bfloat162 p0, p1;
    p0.x = __float2bfloat16(v.x); p0.y = __float2bfloat16(v.y);
    p1.x = __float2bfloat16(v.z); p1.y = __float2bfloat16(v.w);
    __nv_bfloat162* dst = (__nv_bfloat162*)(g_Bbf + (size_t)k * D_DIM + lane * 4);
    dst[0] = p0; dst[1] = p1;
    // zero EMA scratch (replaces init_kernel)
    *(float4*)(g_es + (size_t)k * D_DIM + lane * 4) = make_float4(0.f, 0.f, 0.f, 0.f);
    float s = v.x * v.x + v.y * v.y + v.z * v.z + v.w * v.w;
    for (int o = 16; o; o >>= 1) s += __shfl_xor_sync(0xffffffffu, s, o);
    if (lane == 0) { g_e2[k] = s; g_cs[k] = 0.f; }
}

// ---- GEMM: 128x256 CTA tile, 8 warps of 64x64, K=128 in two 64-slabs ----
// dynamic smem (96 KB): A0 @0 (16K), A1 @16K, B0 @32K (32K), B1 @64K (32K)
// B rows PERMUTED within each 32-row span at fill time:
//   pi(s5) = (s5&16) | (((s5>>1)&3)<<2) | (((s5>>3)&1)<<1) | (s5&1)
// so accumulator fragment (nt, 2*qd+j) maps to warp-local col
//   16*(nt>>1) + 4*qd + 2*(nt&1) + j  -> each thread owns 4x4 CONSECUTIVE cols.
#define A_SLAB 16384
#define B_SLAB 32768
#define GEMM_SMEM 98304

__device__ __forceinline__ void fill_slab(uint32_t s_u, int m0, int n0, int slab, int tid) {
    // A: 128 rows x 128B  (1024 segments)
#pragma unroll
    for (int it = 0; it < 4; ++it) {
        int li = tid + it * 256;
        int row = li >> 3, ch = li & 7;
        uint32_t so = (uint32_t)(row * 128 + ((ch ^ (row & 7)) << 4));
        const __nv_bfloat16* ga = g_Abf + (size_t)(m0 + row) * D_DIM + slab * 64 + ch * 8;
        asm volatile("cp.async.cg.shared.global [%0], [%1], 16;"
                     :: "r"(s_u + slab * A_SLAB + so), "l"(ga));
    }
    // B: 256 rows x 128B  (2048 segments), row-permuted per 32-span
#pragma unroll
    for (int it = 0; it < 8; ++it) {
        int li = tid + it * 256;
        int row = li >> 3, ch = li & 7;
        uint32_t so = (uint32_t)(row * 128 + ((ch ^ (row & 7)) << 4));
        int s5 = row & 31;
        int prow = (row & ~31) |
                   ((s5 & 16) | (((s5 >> 1) & 3) << 2) | (((s5 >> 3) & 1) << 1) | (s5 & 1));
        const __nv_bfloat16* gb = g_Bbf + (size_t)(n0 + prow) * D_DIM + slab * 64 + ch * 8;
        asm volatile("cp.async.cg.shared.global [%0], [%1], 16;"
                     :: "r"(s_u + 2 * A_SLAB + slab * B_SLAB + so), "l"(gb));
    }
    asm volatile("cp.async.commit_group;");
}

__global__ void __launch_bounds__(256, 1) gemm_kernel(float* __restrict__ dist) {
    extern __shared__ char dsm[];
    const uint32_t s_u = smem_u32(dsm);
    const int tid = threadIdx.x, lane = tid & 31, wid = tid >> 5;
    const int bn = blockIdx.x & 31, bm = blockIdx.x >> 5;
    const int m0 = bm * 128, n0 = bn * 256;
    const int wm = wid >> 2, wn = wid & 3;     // warps 2 (M) x 4 (N), warp tile 64x64

    fill_slab(s_u, m0, n0, 0, tid);
    fill_slab(s_u, m0, n0, 1, tid);

    float acc[4][8][4];
#pragma unroll
    for (int a = 0; a < 4; ++a)
#pragma unroll
        for (int b = 0; b < 8; ++b)
#pragma unroll
            for (int c = 0; c < 4; ++c) acc[a][b][c] = 0.f;

#pragma unroll 1
    for (int slab = 0; slab < 2; ++slab) {
        if (slab == 0) asm volatile("cp.async.wait_group 1;");
        else           asm volatile("cp.async.wait_group 0;");
        __syncthreads();
        const uint32_t sA_u = s_u + slab * A_SLAB;
        const uint32_t sB_u = s_u + 2 * A_SLAB + slab * B_SLAB;

#pragma unroll
        for (int kt = 0; kt < 4; ++kt) {
            uint32_t af[4][4];
            uint32_t bfr[8][2];
#pragma unroll
            for (int mt = 0; mt < 4; ++mt) {
                int r = wm * 64 + mt * 16 + (lane & 15);
                int ch = kt * 2 + (lane >> 4);
                uint32_t ad = sA_u + (uint32_t)(r * 128 + ((ch ^ (r & 7)) << 4));
                asm volatile("ldmatrix.sync.aligned.m8n8.x4.shared.b16 {%0,%1,%2,%3}, [%4];"
                    : "=r"(af[mt][0]), "=r"(af[mt][1]), "=r"(af[mt][2]), "=r"(af[mt][3])
                    : "r"(ad));
            }
#pragma unroll
            for (int p = 0; p < 4; ++p) {
                // B n-major == col-major k x n operand -> NON-trans ldmatrix
                int r = wn * 64 + p * 16 + ((lane >> 4) << 3) + (lane & 7);
                int ch = kt * 2 + ((lane >> 3) & 1);
                uint32_t bd = sB_u + (uint32_t)(r * 128 + ((ch ^ (r & 7)) << 4));
                asm volatile("ldmatrix.sync.aligned.m8n8.x4.shared.b16 {%0,%1,%2,%3}, [%4];"
                    : "=r"(bfr[p * 2][0]), "=r"(bfr[p * 2][1]),
                      "=r"(bfr[p * 2 + 1][0]), "=r"(bfr[p * 2 + 1][1])
                    : "r"(bd));
            }
#pragma unroll
            for (int mt = 0; mt < 4; ++mt)
#pragma unroll
                for (int nt = 0; nt < 8; ++nt)
                    asm volatile(
                        "mma.sync.aligned.m16n8k16.row.col.f32.bf16.bf16.f32 "
                        "{%0,%1,%2,%3}, {%4,%5,%6,%7}, {%8,%9}, {%0,%1,%2,%3};"
                        : "+f"(acc[mt][nt][0]), "+f"(acc[mt][nt][1]),
                          "+f"(acc[mt][nt][2]), "+f"(acc[mt][nt][3])
                        : "r"(af[mt][0]), "r"(af[mt][1]), "r"(af[mt][2]), "r"(af[mt][3]),
                          "r"(bfr[nt][0]), "r"(bfr[nt][1]));
        }
    }

    __syncthreads();   // all compute done before reusing smem for min-reduction

    // epilogue: dist = x2 + e2 - 2*dot; thread owns 4 runs of 4 consecutive cols
    // at wcb + g2*16 + 4*qd, g2 in 0..3 (nt pair 2g2, 2g2+1)
    unsigned long long* smin = (unsigned long long*)dsm;
    const int g = lane >> 2, qd = lane & 3;
    const int wcb = n0 + wn * 64;
    float4 e2v[4];
#pragma unroll
    for (int g2 = 0; g2 < 4; ++g2) e2v[g2] = *(const float4*)(g_e2 + wcb + g2 * 16 + 4 * qd);
#pragma unroll
    for (int mt = 0; mt < 4; ++mt) {
#pragma unroll
        for (int h = 0; h < 2; ++h) {
            int lrow = wm * 64 + mt * 16 + h * 8 + g;
            int row = m0 + lrow;
            float x2v = g_x2[row];
            float* dr = dist + (size_t)row * K_CODE + wcb + 4 * qd;
            unsigned long long pk = ~0ull;
#pragma unroll
            for (int g2 = 0; g2 < 4; ++g2) {
                float4 v;
                v.x = fmaf(-2.f, acc[mt][2 * g2][h * 2 + 0], x2v + e2v[g2].x);
                v.y = fmaf(-2.f, acc[mt][2 * g2][h * 2 + 1], x2v + e2v[g2].y);
                v.z = fmaf(-2.f, acc[mt][2 * g2 + 1][h * 2 + 0], x2v + e2v[g2].z);
                v.w = fmaf(-2.f, acc[mt][2 * g2 + 1][h * 2 + 1], x2v + e2v[g2].w);
                *(float4*)(dr + g2 * 16) = v;
                int cb = wcb + g2 * 16 + 4 * qd;
                const float vv[4] = {v.x, v.y, v.z, v.w};
#pragma unroll
                for (int j = 0; j < 4; ++j) {
                    unsigned long long pj =
                        ((unsigned long long)__float_as_uint(vv[j]) << 32) | (unsigned)(cb + j);
                    pk = pj < pk ? pj : pk;
                }
            }
            unsigned long long t1 = __shfl_xor_sync(0xffffffffu, pk, 1);
            pk = t1 < pk ? t1 : pk;
            unsigned long long t2 = __shfl_xor_sync(0xffffffffu, pk, 2);
            pk = t2 < pk ? t2 : pk;
            if (qd == 0) smin[lrow * 4 + wn] = pk;
        }
    }
    __syncthreads();
    if (tid < 128) {
        unsigned long long m01 = smin[tid * 4 + 0] < smin[tid * 4 + 1]
                               ? smin[tid * 4 + 0] : smin[tid * 4 + 1];
        unsigned long long m23 = smin[tid * 4 + 2] < smin[tid * 4 + 3]
                               ? smin[tid * 4 + 2] : smin[tid * 4 + 3];
        g_tbest[(size_t)(m0 + tid) * NTILE2 + bn] = m01 < m23 ? m01 : m23;
    }
}

// ---- pass2: exact fp32 argmin fixup + quantized/indices/EMA scatter ----
__global__ void __launch_bounds__(256) pass2_kernel(
    const float* __restrict__ x, const float* __restrict__ embed,
    const float* __restrict__ dist, float* __restrict__ out_q, float* __restrict__ out_i) {
    const int lane = threadIdx.x & 31;
    const int row = blockIdx.x * 8 + (threadIdx.x >> 5);

    const unsigned long long* tb = g_tbest + (size_t)row * NTILE2;
    unsigned long long e0 = tb[lane];
    unsigned long long mn = e0;
#pragma unroll
    for (int o = 16; o; o >>= 1) {
        unsigned long long t = __shfl_xor_sync(0xffffffffu, mn, o);
        mn = t < mn ? t : mn;
    }
    const float thr = __uint_as_float((unsigned)(mn >> 32)) + 2.0f;  // b* + 2*margin

    const float4 xl4 = *(const float4*)(x + (size_t)row * D_DIM + lane * 4);
    float bestv = 3.402823466e+38f;
    int bestc = 0x7fffffff;

#pragma unroll 1
    for (int t = 0; t < NTILE2; ++t) {
        unsigned long long tv = __shfl_sync(0xffffffffu, e0, t);
        if (__uint_as_float((unsigned)(tv >> 32)) >= thr) continue;
#pragma unroll 1
        for (int half = 0; half < 2; ++half) {
            float4 dv = *(const float4*)(dist + (size_t)row * K_CODE +
                                         t * 256 + half * 128 + lane * 4);
            float dvv[4] = {dv.x, dv.y, dv.z, dv.w};
#pragma unroll
            for (int j = 0; j < 4; ++j) {
                unsigned mask = __ballot_sync(0xffffffffu, dvv[j] < thr);
                while (mask) {
                    int l = __ffs(mask) - 1;
                    mask &= mask - 1;
                    int col = t * 256 + half * 128 + l * 4 + j;
                    float4 ev = *(const float4*)(embed + (size_t)col * D_DIM + lane * 4);
                    float d0 = xl4.x - ev.x, d1 = xl4.y - ev.y;
                    float d2 = xl4.z - ev.z, d3 = xl4.w - ev.w;
                    float s = d0 * d0 + d1 * d1 + d2 * d2 + d3 * d3;
#pragma unroll
                    for (int o = 16; o; o >>= 1) s += __shfl_xor_sync(0xffffffffu, s, o);
                    if (s < bestv || (s == bestv && col < bestc)) { bestv = s; bestc = col; }
                }
            }
        }
    }

    if (lane == 0) {
        out_i[row] = (float)bestc;
        atomicAdd(&g_cs[bestc], 1.0f);
    }
    float4 ev = *(const float4*)(embed + (size_t)bestc * D_DIM + lane * 4);
    *(float4*)(out_q + (size_t)row * D_DIM + lane * 4) = ev;
    float* esr = g_es + (size_t)bestc * D_DIM + lane * 4;
    atomicAdd(esr + 0, xl4.x);
    atomicAdd(esr + 1, xl4.y);
    atomicAdd(esr + 2, xl4.z);
    atomicAdd(esr + 3, xl4.w);
}

__global__ void finalA_kernel(const float* __restrict__ clus, float* __restrict__ out_ncs) {
    int tid = threadIdx.x, lane = tid & 31, wid = tid >> 5;
    float s = 0.f;
    for (int k = tid; k < K_CODE; k += 1024) {
        float v = DECAY * clus[k] + OMD * g_cs[k];
        out_ncs[k] = v;
        s += v;
    }
    for (int o = 16; o; o >>= 1) s += __shfl_xor_sync(0xffffffffu, s, o);
    __shared__ float sred[32];
    if (lane == 0) sred[wid] = s;
    __syncthreads();
    if (wid == 0) {
        float v = sred[lane];
        for (int o = 16; o; o >>= 1) v += __shfl_xor_sync(0xffffffffu, v, o);
        if (lane == 0) g_S = v;
    }
}

__global__ void finalB_kernel(const float* __restrict__ eavg, const float* __restrict__ clus,
                              float* __restrict__ out_nea, float* __restrict__ out_ne) {
    int i = blockIdx.x * blockDim.x + threadIdx.x;   // 0 .. K*D-1
    int k = i >> 7;
    float nea = DECAY * eavg[i] + OMD * g_es[i];
    out_nea[i] = nea;
    float ncs = DECAY * clus[k] + OMD * g_cs[k];
    float norm = (ncs + EPSF) / (g_S + (float)K_CODE * EPSF);
    out_ne[i] = nea / norm;
}

// ---------------- launch ----------------
extern "C" void kernel_launch(void* const* d_in, const int* in_sizes, int n_in,
                              void* d_out, int out_size) {
    (void)in_sizes; (void)n_in; (void)out_size;
    const float* x     = (const float*)d_in[0];
    const float* embed = (const float*)d_in[1];
    const float* clus  = (const float*)d_in[2];
    const float* eavg  = (const float*)d_in[3];
    float* out = (float*)d_out;

    float* out_q    = out;
    float* out_i    = out + OFF_I;
    float* out_dist = out + OFF_DIST;
    float* out_ne   = out + OFF_NE;
    float* out_ncs  = out + OFF_NCS;
    float* out_nea  = out + OFF_NEA;

    static bool attr_set = false;
    if (!attr_set) {
        cudaFuncSetAttribute(gemm_kernel, cudaFuncAttributeMaxDynamicSharedMemorySize,
                             GEMM_SMEM);
        attr_set = true;
    }

    prep_x_kernel<<<T_TOK / 8, 256>>>(x);
    prep_e_kernel<<<K_CODE / 8, 256>>>(embed);
    gemm_kernel<<<(T_TOK / 128) * (K_CODE / 256), 256, GEMM_SMEM>>>(out_dist);
    pass2_kernel<<<T_TOK / 8, 256>>>(x, embed, out_dist, out_q, out_i);
    finalA_kernel<<<1, 1024>>>(clus, out_ncs);
    finalB_kernel<<<(K_CODE * D_DIM) / 256, 256>>>(eavg, clus, out_nea, out_ne);
}

// round 10
// speedup vs baseline: 1.2857x; 1.2857x over previous
#include <cuda_runtime.h>
#include <cuda_bf16.h>
#include <cstdint>

// ---------------- problem constants ----------------
#define T_TOK  32768
#define K_CODE 8192
#define D_DIM  128
#define NTILE  64            // K_CODE / 128 column tiles
#define DECAY  0.1f
#define OMD    0.9f
#define EPSF   1e-5f

// output layout (all fp32, concatenated in reference return order)
static const size_t OFF_I    = (size_t)T_TOK * D_DIM;             // after quantized
static const size_t OFF_DIST = OFF_I + T_TOK;                     // after indices
static const size_t OFF_NE   = OFF_DIST + (size_t)T_TOK * K_CODE; // after dist
static const size_t OFF_NCS  = OFF_NE + (size_t)K_CODE * D_DIM;   // after new_embed
static const size_t OFF_NEA  = OFF_NCS + K_CODE;                  // after new_cluster_size

// ---------------- device scratch (no allocations allowed) ----------------
__device__ __align__(16) __nv_bfloat16 g_Abf[(size_t)T_TOK * D_DIM];   // 8 MB
__device__ __align__(16) __nv_bfloat16 g_Bbf[(size_t)K_CODE * D_DIM];  // 2 MB
__device__ float g_x2[T_TOK];
__device__ float g_e2[K_CODE];
__device__ unsigned long long g_tbest[(size_t)T_TOK * NTILE];          // 16 MB (fully overwritten)
__device__ float g_cs[K_CODE];
__device__ __align__(16) float g_es[(size_t)K_CODE * D_DIM];           // 4 MB
__device__ float g_S;

__device__ __forceinline__ uint32_t smem_u32(const void* p) {
    return (uint32_t)__cvta_generic_to_shared(p);
}

// ---------------- merged prep kernel (warp-per-row, float4) ----------------
// blocks [0, T_TOK/8): tokens;  blocks [T_TOK/8, T_TOK/8 + K_CODE/8): codes
__global__ void __launch_bounds__(256) prep_kernel(const float* __restrict__ x,
                                                   const float* __restrict__ embed) {
    int lane = threadIdx.x & 31;
    if (blockIdx.x < T_TOK / 8) {
        int t = blockIdx.x * 8 + (threadIdx.x >> 5);
        float4 v = *(const float4*)(x + (size_t)t * D_DIM + lane * 4);
        __nv_bfloat162 p0, p1;
        p0.x = __float2bfloat16(v.x); p0.y = __float2bfloat16(v.y);
        p1.x = __float2bfloat16(v.z); p1.y = __float2bfloat16(v.w);
        __nv_bfloat162* dst = (__nv_bfloat162*)(g_Abf + (size_t)t * D_DIM + lane * 4);
        dst[0] = p0; dst[1] = p1;
        float s = v.x * v.x + v.y * v.y + v.z * v.z + v.w * v.w;
        for (int o = 16; o; o >>= 1) s += __shfl_xor_sync(0xffffffffu, s, o);
        if (lane == 0) g_x2[t] = s;
    } else {
        int k = (blockIdx.x - T_TOK / 8) * 8 + (threadIdx.x >> 5);
        float4 v = *(const float4*)(embed + (size_t)k * D_DIM + lane * 4);
        __nv_bfloat162 p0, p1;
        p0.x = __float2bfloat16(v.x); p0.y = __float2bfloat16(v.y);
        p1.x = __float2bfloat16(v.z); p1.y = __float2bfloat16(v.w);
        __nv_bfloat162* dst = (__nv_bfloat162*)(g_Bbf + (size_t)k * D_DIM + lane * 4);
        dst[0] = p0; dst[1] = p1;
        *(float4*)(g_es + (size_t)k * D_DIM + lane * 4) = make_float4(0.f, 0.f, 0.f, 0.f);
        float s = v.x * v.x + v.y * v.y + v.z * v.z + v.w * v.w;
        for (int o = 16; o; o >>= 1) s += __shfl_xor_sync(0xffffffffu, s, o);
        if (lane == 0) { g_e2[k] = s; g_cs[k] = 0.f; }
    }
}

// ---- GEMM: 128x128 CTA tile, K=128 in two 64-slabs, both prefetched ----
// dynamic smem: A0 @0, B0 @16K, A1 @32K, B1 @48K  (64 KB total)
// B rows PERMUTED within each 32-row span at fill time:
//   pi(s5) = (s5&16) | (((s5>>1)&3)<<2) | (((s5>>3)&1)<<1) | (s5&1)
// so accumulator fragment (nt, 2*qd+j) maps to warp-local col
//   16*(nt>>1) + 4*qd + 2*(nt&1) + j  -> each thread owns 8 CONSECUTIVE cols.
#define SLAB_BYTES 16384
#define GEMM_SMEM  65536

__device__ __forceinline__ void fill_slab(uint32_t sA_u, uint32_t sB_u,
                                          int m0, int n0, int slab, int tid) {
#pragma unroll
    for (int it = 0; it < 4; ++it) {
        int s = tid + it * 256;
        int row = s >> 3, ch = s & 7;
        uint32_t so = (uint32_t)(row * 128 + ((ch ^ (row & 7)) << 4));
        const __nv_bfloat16* ga = g_Abf + (size_t)(m0 + row) * D_DIM + slab * 64 + ch * 8;
        asm volatile("cp.async.cg.shared.global [%0], [%1], 16;" :: "r"(sA_u + so), "l"(ga));
        int s5 = row & 31;
        int prow = (row & 96) |
                   ((s5 & 16) | (((s5 >> 1) & 3) << 2) | (((s5 >> 3) & 1) << 1) | (s5 & 1));
        const __nv_bfloat16* gb = g_Bbf + (size_t)(n0 + prow) * D_DIM + slab * 64 + ch * 8;
        asm volatile("cp.async.cg.shared.global [%0], [%1], 16;" :: "r"(sB_u + so), "l"(gb));
    }
    asm volatile("cp.async.commit_group;");
}

__global__ void __launch_bounds__(256, 2) gemm_kernel(float* __restrict__ dist) {
    extern __shared__ char dsm[];
    const uint32_t s_u = smem_u32(dsm);
    const int tid = threadIdx.x, lane = tid & 31, wid = tid >> 5;
    const int bn = blockIdx.x & 63, bm = blockIdx.x >> 6;
    const int m0 = bm * 128, n0 = bn * 128;
    const int wm = wid >> 2, wn = wid & 3;     // warps 2 (M) x 4 (N), warp tile 64x32

    // prefetch BOTH K-slabs (two commit groups)
    fill_slab(s_u, s_u + SLAB_BYTES, m0, n0, 0, tid);
    fill_slab(s_u + 2 * SLAB_BYTES, s_u + 3 * SLAB_BYTES, m0, n0, 1, tid);

    float acc[4][4][4];
#pragma unroll
    for (int a = 0; a < 4; ++a)
#pragma unroll
        for (int b = 0; b < 4; ++b)
#pragma unroll
            for (int c = 0; c < 4; ++c) acc[a][b][c] = 0.f;

#pragma unroll 1
    for (int slab = 0; slab < 2; ++slab) {
        if (slab == 0) asm volatile("cp.async.wait_group 1;");
        else           asm volatile("cp.async.wait_group 0;");
        __syncthreads();
        const uint32_t sA_u = s_u + slab * 2 * SLAB_BYTES;
        const uint32_t sB_u = sA_u + SLAB_BYTES;

#pragma unroll
        for (int kt = 0; kt < 4; ++kt) {
            uint32_t af[4][4];
            uint32_t bfr[4][2];
#pragma unroll
            for (int mt = 0; mt < 4; ++mt) {
                int r = wm * 64 + mt * 16 + (lane & 15);
                int ch = kt * 2 + (lane >> 4);
                uint32_t ad = sA_u + (uint32_t)(r * 128 + ((ch ^ (r & 7)) << 4));
                asm volatile("ldmatrix.sync.aligned.m8n8.x4.shared.b16 {%0,%1,%2,%3}, [%4];"
                    : "=r"(af[mt][0]), "=r"(af[mt][1]), "=r"(af[mt][2]), "=r"(af[mt][3])
                    : "r"(ad));
            }
#pragma unroll
            for (int p = 0; p < 2; ++p) {
                // B n-major == col-major k x n operand -> NON-trans ldmatrix;
                // column permutation lives in smem content
                int r = wn * 32 + p * 16 + ((lane >> 4) << 3) + (lane & 7);
                int ch = kt * 2 + ((lane >> 3) & 1);
                uint32_t bd = sB_u + (uint32_t)(r * 128 + ((ch ^ (r & 7)) << 4));
                asm volatile("ldmatrix.sync.aligned.m8n8.x4.shared.b16 {%0,%1,%2,%3}, [%4];"
                    : "=r"(bfr[p * 2][0]), "=r"(bfr[p * 2][1]),
                      "=r"(bfr[p * 2 + 1][0]), "=r"(bfr[p * 2 + 1][1])
                    : "r"(bd));
            }
#pragma unroll
            for (int mt = 0; mt < 4; ++mt)
#pragma unroll
                for (int nt = 0; nt < 4; ++nt)
                    asm volatile(
                        "mma.sync.aligned.m16n8k16.row.col.f32.bf16.bf16.f32 "
                        "{%0,%1,%2,%3}, {%4,%5,%6,%7}, {%8,%9}, {%0,%1,%2,%3};"
                        : "+f"(acc[mt][nt][0]), "+f"(acc[mt][nt][1]),
                          "+f"(acc[mt][nt][2]), "+f"(acc[mt][nt][3])
                        : "r"(af[mt][0]), "r"(af[mt][1]), "r"(af[mt][2]), "r"(af[mt][3]),
                          "r"(bfr[nt][0]), "r"(bfr[nt][1]));
        }
    }

    // epilogue: dist = x2 + e2 - 2*dot; each thread owns 8 consecutive cols
    // at cb = n0 + wn*32 + 4*qd (cols cb..cb+3) and cb+16 (cols cb+16..cb+19)
    unsigned long long* smin = (unsigned long long*)dsm;   // reuse slab0 region
    const int g = lane >> 2, qd = lane & 3;
    const int cb = n0 + wn * 32 + 4 * qd;
    const float4 e2a = *(const float4*)(g_e2 + cb);
    const float4 e2b = *(const float4*)(g_e2 + cb + 16);
#pragma unroll
    for (int mt = 0; mt < 4; ++mt) {
#pragma unroll
        for (int h = 0; h < 2; ++h) {
            int lrow = wm * 64 + mt * 16 + h * 8 + g;
            int row = m0 + lrow;
            float x2v = g_x2[row];
            float4 va, vb;
            va.x = fmaf(-2.f, acc[mt][0][h * 2 + 0], x2v + e2a.x);
            va.y = fmaf(-2.f, acc[mt][0][h * 2 + 1], x2v + e2a.y);
            va.z = fmaf(-2.f, acc[mt][1][h * 2 + 0], x2v + e2a.z);
            va.w = fmaf(-2.f, acc[mt][1][h * 2 + 1], x2v + e2a.w);
            vb.x = fmaf(-2.f, acc[mt][2][h * 2 + 0], x2v + e2b.x);
            vb.y = fmaf(-2.f, acc[mt][2][h * 2 + 1], x2v + e2b.y);
            vb.z = fmaf(-2.f, acc[mt][3][h * 2 + 0], x2v + e2b.z);
            vb.w = fmaf(-2.f, acc[mt][3][h * 2 + 1], x2v + e2b.w);
            float* dr = dist + (size_t)row * K_CODE + cb;
            // streaming stores: dist is written once, rarely re-read
            asm volatile("st.global.cs.v4.f32 [%0], {%1,%2,%3,%4};"
                         :: "l"(dr), "f"(va.x), "f"(va.y), "f"(va.z), "f"(va.w) : "memory");
            asm volatile("st.global.cs.v4.f32 [%0], {%1,%2,%3,%4};"
                         :: "l"(dr + 16), "f"(vb.x), "f"(vb.y), "f"(vb.z), "f"(vb.w) : "memory");
            unsigned long long pk = ~0ull;
            {
                const float vv[8] = {va.x, va.y, va.z, va.w, vb.x, vb.y, vb.z, vb.w};
#pragma unroll
                for (int j = 0; j < 8; ++j) {
                    int col = cb + (j < 4 ? j : 12 + j);   // +16 offset for second group
                    unsigned long long pj =
                        ((unsigned long long)__float_as_uint(vv[j]) << 32) | (unsigned)col;
                    pk = pj < pk ? pj : pk;
                }
            }
            unsigned long long t1 = __shfl_xor_sync(0xffffffffu, pk, 1);
            pk = t1 < pk ? t1 : pk;
            unsigned long long t2 = __shfl_xor_sync(0xffffffffu, pk, 2);
            pk = t2 < pk ? t2 : pk;
            if (qd == 0) smin[lrow * 4 + wn] = pk;
        }
    }
    __syncthreads();
    if (tid < 128) {
        unsigned long long m01 = smin[tid * 4 + 0] < smin[tid * 4 + 1]
                               ? smin[tid * 4 + 0] : smin[tid * 4 + 1];
        unsigned long long m23 = smin[tid * 4 + 2] < smin[tid * 4 + 3]
                               ? smin[tid * 4 + 2] : smin[tid * 4 + 3];
        g_tbest[(size_t)(m0 + tid) * NTILE + bn] = m01 < m23 ? m01 : m23;
    }
}

// ---- pass2: exact fp32 argmin fixup + quantized/indices/EMA scatter ----
// tile candidate selection via ballot (no serial 64-iter scan)
__global__ void __launch_bounds__(256) pass2_kernel(
    const float* __restrict__ x, const float* __restrict__ embed,
    const float* __restrict__ dist, float* __restrict__ out_q, float* __restrict__ out_i) {
    const int lane = threadIdx.x & 31;
    const int row = blockIdx.x * 8 + (threadIdx.x >> 5);

    const unsigned long long* tb = g_tbest + (size_t)row * NTILE;
    unsigned long long e0 = tb[lane], e1 = tb[lane + 32];
    unsigned long long mn = e0 < e1 ? e0 : e1;
#pragma unroll
    for (int o = 16; o; o >>= 1) {
        unsigned long long t = __shfl_xor_sync(0xffffffffu, mn, o);
        mn = t < mn ? t : mn;
    }
    const float thr = __uint_as_float((unsigned)(mn >> 32)) + 2.0f;  // b* + 2*margin

    // candidate-tile bitmasks: lane L tests tiles L and L+32
    unsigned cand0 = __ballot_sync(0xffffffffu, __uint_as_float((unsigned)(e0 >> 32)) < thr);
    unsigned cand1 = __ballot_sync(0xffffffffu, __uint_as_float((unsigned)(e1 >> 32)) < thr);

    const float4 xl4 = *(const float4*)(x + (size_t)row * D_DIM + lane * 4);
    float bestv = 3.402823466e+38f;
    int bestc = 0x7fffffff;

#pragma unroll 1
    for (int grp = 0; grp < 2; ++grp) {
        unsigned cm = grp ? cand1 : cand0;
        while (cm) {
            int t = __ffs(cm) - 1;
            cm &= cm - 1;
            int tile = grp * 32 + t;
            float4 dv = *(const float4*)(dist + (size_t)row * K_CODE + tile * 128 + lane * 4);
            float dvv[4] = {dv.x, dv.y, dv.z, dv.w};
#pragma unroll
            for (int j = 0; j < 4; ++j) {
                unsigned mask = __ballot_sync(0xffffffffu, dvv[j] < thr);
                while (mask) {
                    int l = __ffs(mask) - 1;
                    mask &= mask - 1;
                    int col = tile * 128 + l * 4 + j;
                    float4 ev = *(const float4*)(embed + (size_t)col * D_DIM + lane * 4);
                    float d0 = xl4.x - ev.x, d1 = xl4.y - ev.y;
                    float d2 = xl4.z - ev.z, d3 = xl4.w - ev.w;
                    float s = d0 * d0 + d1 * d1 + d2 * d2 + d3 * d3;
#pragma unroll
                    for (int o = 16; o; o >>= 1) s += __shfl_xor_sync(0xffffffffu, s, o);
                    if (s < bestv || (s == bestv && col < bestc)) { bestv = s; bestc = col; }
                }
            }
        }
    }

    if (lane == 0) {
        out_i[row] = (float)bestc;
        atomicAdd(&g_cs[bestc], 1.0f);
    }
    float4 ev = *(const float4*)(embed + (size_t)bestc * D_DIM + lane * 4);
    *(float4*)(out_q + (size_t)row * D_DIM + lane * 4) = ev;
    float* esr = g_es + (size_t)bestc * D_DIM + lane * 4;
    atomicAdd(esr + 0, xl4.x);
    atomicAdd(esr + 1, xl4.y);
    atomicAdd(esr + 2, xl4.z);
    atomicAdd(esr + 3, xl4.w);
}

__global__ void finalA_kernel(const float* __restrict__ clus, float* __restrict__ out_ncs) {
    int tid = threadIdx.x, lane = tid & 31, wid = tid >> 5;
    float s = 0.f;
    for (int k = tid; k < K_CODE; k += 1024) {
        float v = DECAY * clus[k] + OMD * g_cs[k];
        out_ncs[k] = v;
        s += v;
    }
    for (int o = 16; o; o >>= 1) s += __shfl_xor_sync(0xffffffffu, s, o);
    __shared__ float sred[32];
    if (lane == 0) sred[wid] = s;
    __syncthreads();
    if (wid == 0) {
        float v = sred[lane];
        for (int o = 16; o; o >>= 1) v += __shfl_xor_sync(0xffffffffu, v, o);
        if (lane == 0) g_S = v;
    }
}

__global__ void finalB_kernel(const float* __restrict__ eavg, const float* __restrict__ clus,
                              float* __restrict__ out_nea, float* __restrict__ out_ne) {
    int i = blockIdx.x * blockDim.x + threadIdx.x;   // 0 .. K*D-1
    int k = i >> 7;
    float nea = DECAY * eavg[i] + OMD * g_es[i];
    out_nea[i] = nea;
    float ncs = DECAY * clus[k] + OMD * g_cs[k];
    float norm = (ncs + EPSF) / (g_S + (float)K_CODE * EPSF);
    out_ne[i] = nea / norm;
}

// ---------------- launch ----------------
extern "C" void kernel_launch(void* const* d_in, const int* in_sizes, int n_in,
                              void* d_out, int out_size) {
    (void)in_sizes; (void)n_in; (void)out_size;
    const float* x     = (const float*)d_in[0];
    const float* embed = (const float*)d_in[1];
    const float* clus  = (const float*)d_in[2];
    const float* eavg  = (const float*)d_in[3];
    float* out = (float*)d_out;

    float* out_q    = out;
    float* out_i    = out + OFF_I;
    float* out_dist = out + OFF_DIST;
    float* out_ne   = out + OFF_NE;
    float* out_ncs  = out + OFF_NCS;
    float* out_nea  = out + OFF_NEA;

    static bool attr_set = false;
    if (!attr_set) {
        cudaFuncSetAttribute(gemm_kernel, cudaFuncAttributeMaxDynamicSharedMemorySize,
                             GEMM_SMEM);
        attr_set = true;
    }

    prep_kernel<<<T_TOK / 8 + K_CODE / 8, 256>>>(x, embed);
    gemm_kernel<<<(T_TOK / 128) * (K_CODE / 128), 256, GEMM_SMEM>>>(out_dist);
    pass2_kernel<<<T_TOK / 8, 256>>>(x, embed, out_dist, out_q, out_i);
    finalA_kernel<<<1, 1024>>>(clus, out_ncs);
    finalB_kernel<<<(K_CODE * D_DIM) / 256, 256>>>(eavg, clus, out_nea, out_ne);
}

// round 11
// speedup vs baseline: 1.3414x; 1.0433x over previous
#include <cuda_runtime.h>
#include <cuda_bf16.h>
#include <cstdint>

// ---------------- problem constants ----------------
#define T_TOK  32768
#define K_CODE 8192
#define D_DIM  128
#define NTILE  64            // K_CODE / 128 column tiles
#define NTILES_TOTAL ((T_TOK / 128) * (K_CODE / 128))   // 16384
#define DECAY  0.1f
#define OMD    0.9f
#define EPSF   1e-5f

// output layout (all fp32, concatenated in reference return order)
static const size_t OFF_I    = (size_t)T_TOK * D_DIM;             // after quantized
static const size_t OFF_DIST = OFF_I + T_TOK;                     // after indices
static const size_t OFF_NE   = OFF_DIST + (size_t)T_TOK * K_CODE; // after dist
static const size_t OFF_NCS  = OFF_NE + (size_t)K_CODE * D_DIM;   // after new_embed
static const size_t OFF_NEA  = OFF_NCS + K_CODE;                  // after new_cluster_size

// ---------------- device scratch (no allocations allowed) ----------------
__device__ __align__(16) __nv_bfloat16 g_Abf[(size_t)T_TOK * D_DIM];   // 8 MB
__device__ __align__(16) __nv_bfloat16 g_Bbf[(size_t)K_CODE * D_DIM];  // 2 MB
__device__ float g_x2[T_TOK];
__device__ float g_e2[K_CODE];
__device__ unsigned long long g_tbest[(size_t)T_TOK * NTILE];          // 16 MB (fully overwritten)
__device__ float g_cs[K_CODE];
__device__ __align__(16) float g_es[(size_t)K_CODE * D_DIM];           // 4 MB
__device__ float g_S;

__device__ __forceinline__ uint32_t smem_u32(const void* p) {
    return (uint32_t)__cvta_generic_to_shared(p);
}

// ---------------- merged prep kernel (warp-per-row, float4) ----------------
// blocks [0, T_TOK/8): tokens;  blocks [T_TOK/8, T_TOK/8 + K_CODE/8): codes
__global__ void __launch_bounds__(256) prep_kernel(const float* __restrict__ x,
                                                   const float* __restrict__ embed) {
    int lane = threadIdx.x & 31;
    if (blockIdx.x == 0 && threadIdx.x == 0) g_S = 0.f;
    if (blockIdx.x < T_TOK / 8) {
        int t = blockIdx.x * 8 + (threadIdx.x >> 5);
        float4 v = *(const float4*)(x + (size_t)t * D_DIM + lane * 4);
        __nv_bfloat162 p0, p1;
        p0.x = __float2bfloat16(v.x); p0.y = __float2bfloat16(v.y);
        p1.x = __float2bfloat16(v.z); p1.y = __float2bfloat16(v.w);
        __nv_bfloat162* dst = (__nv_bfloat162*)(g_Abf + (size_t)t * D_DIM + lane * 4);
        dst[0] = p0; dst[1] = p1;
        float s = v.x * v.x + v.y * v.y + v.z * v.z + v.w * v.w;
        for (int o = 16; o; o >>= 1) s += __shfl_xor_sync(0xffffffffu, s, o);
        if (lane == 0) g_x2[t] = s;
    } else {
        int k = (blockIdx.x - T_TOK / 8) * 8 + (threadIdx.x >> 5);
        float4 v = *(const float4*)(embed + (size_t)k * D_DIM + lane * 4);
        __nv_bfloat162 p0, p1;
        p0.x = __float2bfloat16(v.x); p0.y = __float2bfloat16(v.y);
        p1.x = __float2bfloat16(v.z); p1.y = __float2bfloat16(v.w);
        __nv_bfloat162* dst = (__nv_bfloat162*)(g_Bbf + (size_t)k * D_DIM + lane * 4);
        dst[0] = p0; dst[1] = p1;
        *(float4*)(g_es + (size_t)k * D_DIM + lane * 4) = make_float4(0.f, 0.f, 0.f, 0.f);
        float s = v.x * v.x + v.y * v.y + v.z * v.z + v.w * v.w;
        for (int o = 16; o; o >>= 1) s += __shfl_xor_sync(0xffffffffu, s, o);
        if (lane == 0) { g_e2[k] = s; g_cs[k] = 0.f; }
    }
}

// ---- persistent GEMM: 128x128 tiles, K in 64-chunks through a 3-stage ring ----
// stage s (s=0..2): A @ s*32K (16K), B @ s*32K+16K (16K).  smin @ 96K (4KB).
// B rows PERMUTED within each 32-row span at fill time:
//   pi(s5) = (s5&16) | (((s5>>1)&3)<<2) | (((s5>>3)&1)<<1) | (s5&1)
// so accumulator fragment (nt, 2*qd+j) maps to warp-local col
//   16*(nt>>1) + 4*qd + 2*(nt&1) + j  -> each thread owns 8 CONSECUTIVE cols.
#define STAGE_BYTES 32768
#define SMIN_OFF    98304
#define GEMM_SMEM   102400

__device__ __forceinline__ void fill_chunk(uint32_t s_u, int q, int bid, int grid, int tid) {
    int tile = bid + (q >> 1) * grid;
    int slab = q & 1;
    int m0 = (tile >> 6) * 128, n0 = (tile & 63) * 128;
    uint32_t sA_u = s_u + (q % 3) * STAGE_BYTES;
    uint32_t sB_u = sA_u + 16384;
#pragma unroll
    for (int it = 0; it < 4; ++it) {
        int s = tid + it * 256;
        int row = s >> 3, ch = s & 7;
        uint32_t so = (uint32_t)(row * 128 + ((ch ^ (row & 7)) << 4));
        const __nv_bfloat16* ga = g_Abf + (size_t)(m0 + row) * D_DIM + slab * 64 + ch * 8;
        asm volatile("cp.async.cg.shared.global [%0], [%1], 16;" :: "r"(sA_u + so), "l"(ga));
        int s5 = row & 31;
        int prow = (row & 96) |
                   ((s5 & 16) | (((s5 >> 1) & 3) << 2) | (((s5 >> 3) & 1) << 1) | (s5 & 1));
        const __nv_bfloat16* gb = g_Bbf + (size_t)(n0 + prow) * D_DIM + slab * 64 + ch * 8;
        asm volatile("cp.async.cg.shared.global [%0], [%1], 16;" :: "r"(sB_u + so), "l"(gb));
    }
    asm volatile("cp.async.commit_group;");
}

__global__ void __launch_bounds__(256) gemm_kernel(float* __restrict__ dist, int grid) {
    extern __shared__ char dsm[];
    const uint32_t s_u = smem_u32(dsm);
    const int tid = threadIdx.x, lane = tid & 31, wid = tid >> 5;
    const int bid = blockIdx.x;
    const int wm = wid >> 2, wn = wid & 3;     // warps 2 (M) x 4 (N), warp tile 64x32
    const int g = lane >> 2, qd = lane & 3;
    unsigned long long* smin = (unsigned long long*)(dsm + SMIN_OFF);

    const int nlt = (NTILES_TOTAL - bid + grid - 1) / grid;   // local tiles
    const int Q = nlt * 2;                                     // local 64-K chunks

    // prologue: prefetch chunks 0 and 1
    fill_chunk(s_u, 0, bid, grid, tid);
    fill_chunk(s_u, 1, bid, grid, tid);

    float acc[4][4][4];
#pragma unroll
    for (int a = 0; a < 4; ++a)
#pragma unroll
        for (int b = 0; b < 4; ++b)
#pragma unroll
            for (int c = 0; c < 4; ++c) acc[a][b][c] = 0.f;

#pragma unroll 1
    for (int q = 0; q < Q; ++q) {
        if (q + 2 < Q) {
            fill_chunk(s_u, q + 2, bid, grid, tid);
            asm volatile("cp.async.wait_group 2;");
        } else if (q + 2 == Q) {
            asm volatile("cp.async.wait_group 1;");
        } else {
            asm volatile("cp.async.wait_group 0;");
        }
        __syncthreads();

        const uint32_t sA_u = s_u + (q % 3) * STAGE_BYTES;
        const uint32_t sB_u = sA_u + 16384;
#pragma unroll
        for (int kt = 0; kt < 4; ++kt) {
            uint32_t af[4][4];
            uint32_t bfr[4][2];
#pragma unroll
            for (int mt = 0; mt < 4; ++mt) {
                int r = wm * 64 + mt * 16 + (lane & 15);
                int ch = kt * 2 + (lane >> 4);
                uint32_t ad = sA_u + (uint32_t)(r * 128 + ((ch ^ (r & 7)) << 4));
                asm volatile("ldmatrix.sync.aligned.m8n8.x4.shared.b16 {%0,%1,%2,%3}, [%4];"
                    : "=r"(af[mt][0]), "=r"(af[mt][1]), "=r"(af[mt][2]), "=r"(af[mt][3])
                    : "r"(ad));
            }
#pragma unroll
            for (int p = 0; p < 2; ++p) {
                // B n-major == col-major k x n operand -> NON-trans ldmatrix;
                // column permutation lives in smem content
                int r = wn * 32 + p * 16 + ((lane >> 4) << 3) + (lane & 7);
                int ch = kt * 2 + ((lane >> 3) & 1);
                uint32_t bd = sB_u + (uint32_t)(r * 128 + ((ch ^ (r & 7)) << 4));
                asm volatile("ldmatrix.sync.aligned.m8n8.x4.shared.b16 {%0,%1,%2,%3}, [%4];"
                    : "=r"(bfr[p * 2][0]), "=r"(bfr[p * 2][1]),
                      "=r"(bfr[p * 2 + 1][0]), "=r"(bfr[p * 2 + 1][1])
                    : "r"(bd));
            }
#pragma unroll
            for (int mt = 0; mt < 4; ++mt)
#pragma unroll
                for (int nt = 0; nt < 4; ++nt)
                    asm volatile(
                        "mma.sync.aligned.m16n8k16.row.col.f32.bf16.bf16.f32 "
                        "{%0,%1,%2,%3}, {%4,%5,%6,%7}, {%8,%9}, {%0,%1,%2,%3};"
                        : "+f"(acc[mt][nt][0]), "+f"(acc[mt][nt][1]),
                          "+f"(acc[mt][nt][2]), "+f"(acc[mt][nt][3])
                        : "r"(af[mt][0]), "r"(af[mt][1]), "r"(af[mt][2]), "r"(af[mt][3]),
                          "r"(bfr[nt][0]), "r"(bfr[nt][1]));
        }

        if (q & 1) {
            // tile complete -> epilogue (overlaps with in-flight fill of chunk q+2)
            int tile = bid + (q >> 1) * grid;
            int bn = tile & 63, m0 = (tile >> 6) * 128, n0 = bn * 128;
            const int cb = n0 + wn * 32 + 4 * qd;
            const float4 e2a = *(const float4*)(g_e2 + cb);
            const float4 e2b = *(const float4*)(g_e2 + cb + 16);
#pragma unroll
            for (int mt = 0; mt < 4; ++mt) {
#pragma unroll
                for (int h = 0; h < 2; ++h) {
                    int lrow = wm * 64 + mt * 16 + h * 8 + g;
                    int row = m0 + lrow;
                    float x2v = g_x2[row];
                    float4 va, vb;
                    va.x = fmaf(-2.f, acc[mt][0][h * 2 + 0], x2v + e2a.x);
                    va.y = fmaf(-2.f, acc[mt][0][h * 2 + 1], x2v + e2a.y);
                    va.z = fmaf(-2.f, acc[mt][1][h * 2 + 0], x2v + e2a.z);
                    va.w = fmaf(-2.f, acc[mt][1][h * 2 + 1], x2v + e2a.w);
                    vb.x = fmaf(-2.f, acc[mt][2][h * 2 + 0], x2v + e2b.x);
                    vb.y = fmaf(-2.f, acc[mt][2][h * 2 + 1], x2v + e2b.y);
                    vb.z = fmaf(-2.f, acc[mt][3][h * 2 + 0], x2v + e2b.z);
                    vb.w = fmaf(-2.f, acc[mt][3][h * 2 + 1], x2v + e2b.w);
                    float* dr = dist + (size_t)row * K_CODE + cb;
                    asm volatile("st.global.cs.v4.f32 [%0], {%1,%2,%3,%4};"
                                 :: "l"(dr), "f"(va.x), "f"(va.y), "f"(va.z), "f"(va.w)
                                 : "memory");
                    asm volatile("st.global.cs.v4.f32 [%0], {%1,%2,%3,%4};"
                                 :: "l"(dr + 16), "f"(vb.x), "f"(vb.y), "f"(vb.z), "f"(vb.w)
                                 : "memory");
                    unsigned long long pk = ~0ull;
                    {
                        const float vv[8] = {va.x, va.y, va.z, va.w, vb.x, vb.y, vb.z, vb.w};
#pragma unroll
                        for (int j = 0; j < 8; ++j) {
                            int col = cb + (j < 4 ? j : 12 + j);
                            unsigned long long pj =
                                ((unsigned long long)__float_as_uint(vv[j]) << 32) |
                                (unsigned)col;
                            pk = pj < pk ? pj : pk;
                        }
                    }
                    unsigned long long t1 = __shfl_xor_sync(0xffffffffu, pk, 1);
                    pk = t1 < pk ? t1 : pk;
                    unsigned long long t2 = __shfl_xor_sync(0xffffffffu, pk, 2);
                    pk = t2 < pk ? t2 : pk;
                    if (qd == 0) smin[lrow * 4 + wn] = pk;
                    // reset accumulators for next tile
#pragma unroll
                    for (int nt = 0; nt < 4; ++nt) {
                        acc[mt][nt][h * 2 + 0] = 0.f;
                        acc[mt][nt][h * 2 + 1] = 0.f;
                    }
                }
            }
            __syncthreads();
            if (tid < 128) {
                unsigned long long m01 = smin[tid * 4 + 0] < smin[tid * 4 + 1]
                                       ? smin[tid * 4 + 0] : smin[tid * 4 + 1];
                unsigned long long m23 = smin[tid * 4 + 2] < smin[tid * 4 + 3]
                                       ? smin[tid * 4 + 2] : smin[tid * 4 + 3];
                g_tbest[(size_t)(m0 + tid) * NTILE + bn] = m01 < m23 ? m01 : m23;
            }
        }
        __syncthreads();   // stage (q%3) free for refill at iteration q+1
    }
}

// ---- pass2: exact fp32 argmin fixup + quantized/indices/EMA scatter ----
__global__ void __launch_bounds__(256) pass2_kernel(
    const float* __restrict__ x, const float* __restrict__ embed,
    const float* __restrict__ dist, float* __restrict__ out_q, float* __restrict__ out_i) {
    const int lane = threadIdx.x & 31;
    const int row = blockIdx.x * 8 + (threadIdx.x >> 5);

    const unsigned long long* tb = g_tbest + (size_t)row * NTILE;
    unsigned long long e0 = tb[lane], e1 = tb[lane + 32];
    unsigned long long mn = e0 < e1 ? e0 : e1;
#pragma unroll
    for (int o = 16; o; o >>= 1) {
        unsigned long long t = __shfl_xor_sync(0xffffffffu, mn, o);
        mn = t < mn ? t : mn;
    }
    const float thr = __uint_as_float((unsigned)(mn >> 32)) + 2.0f;  // b* + 2*margin

    unsigned cand0 = __ballot_sync(0xffffffffu, __uint_as_float((unsigned)(e0 >> 32)) < thr);
    unsigned cand1 = __ballot_sync(0xffffffffu, __uint_as_float((unsigned)(e1 >> 32)) < thr);

    const float4 xl4 = *(const float4*)(x + (size_t)row * D_DIM + lane * 4);
    float bestv = 3.402823466e+38f;
    int bestc = 0x7fffffff;

#pragma unroll 1
    for (int grp = 0; grp < 2; ++grp) {
        unsigned cm = grp ? cand1 : cand0;
        while (cm) {
            int t = __ffs(cm) - 1;
            cm &= cm - 1;
            int tile = grp * 32 + t;
            float4 dv = *(const float4*)(dist + (size_t)row * K_CODE + tile * 128 + lane * 4);
            float dvv[4] = {dv.x, dv.y, dv.z, dv.w};
#pragma unroll
            for (int j = 0; j < 4; ++j) {
                unsigned mask = __ballot_sync(0xffffffffu, dvv[j] < thr);
                while (mask) {
                    int l = __ffs(mask) - 1;
                    mask &= mask - 1;
                    int col = tile * 128 + l * 4 + j;
                    float4 ev = *(const float4*)(embed + (size_t)col * D_DIM + lane * 4);
                    float d0 = xl4.x - ev.x, d1 = xl4.y - ev.y;
                    float d2 = xl4.z - ev.z, d3 = xl4.w - ev.w;
                    float s = d0 * d0 + d1 * d1 + d2 * d2 + d3 * d3;
#pragma unroll
                    for (int o = 16; o; o >>= 1) s += __shfl_xor_sync(0xffffffffu, s, o);
                    if (s < bestv || (s == bestv && col < bestc)) { bestv = s; bestc = col; }
                }
            }
        }
    }

    if (lane == 0) {
        out_i[row] = (float)bestc;
        atomicAdd(&g_cs[bestc], 1.0f);
    }
    float4 ev = *(const float4*)(embed + (size_t)bestc * D_DIM + lane * 4);
    *(float4*)(out_q + (size_t)row * D_DIM + lane * 4) = ev;
    float* esr = g_es + (size_t)bestc * D_DIM + lane * 4;
    atomicAdd(esr + 0, xl4.x);
    atomicAdd(esr + 1, xl4.y);
    atomicAdd(esr + 2, xl4.z);
    atomicAdd(esr + 3, xl4.w);
}

// multi-block: ncs write + global sum via atomics (g_S zeroed in prep)
__global__ void __launch_bounds__(256) finalA_kernel(const float* __restrict__ clus,
                                                     float* __restrict__ out_ncs) {
    int k = blockIdx.x * 256 + threadIdx.x;
    int lane = threadIdx.x & 31, wid = threadIdx.x >> 5;
    float v = DECAY * clus[k] + OMD * g_cs[k];
    out_ncs[k] = v;
    float s = v;
    for (int o = 16; o; o >>= 1) s += __shfl_xor_sync(0xffffffffu, s, o);
    __shared__ float sred[8];
    if (lane == 0) sred[wid] = s;
    __syncthreads();
    if (threadIdx.x == 0) {
        float b = sred[0] + sred[1] + sred[2] + sred[3]
                + sred[4] + sred[5] + sred[6] + sred[7];
        atomicAdd(&g_S, b);
    }
}

__global__ void finalB_kernel(const float* __restrict__ eavg, const float* __restrict__ clus,
                              float* __restrict__ out_nea, float* __restrict__ out_ne) {
    int i = blockIdx.x * blockDim.x + threadIdx.x;   // 0 .. K*D-1
    int k = i >> 7;
    float nea = DECAY * eavg[i] + OMD * g_es[i];
    out_nea[i] = nea;
    float ncs = DECAY * clus[k] + OMD * g_cs[k];
    float norm = (ncs + EPSF) / (g_S + (float)K_CODE * EPSF);
    out_ne[i] = nea / norm;
}

// ---------------- launch ----------------
extern "C" void kernel_launch(void* const* d_in, const int* in_sizes, int n_in,
                              void* d_out, int out_size) {
    (void)in_sizes; (void)n_in; (void)out_size;
    const float* x     = (const float*)d_in[0];
    const float* embed = (const float*)d_in[1];
    const float* clus  = (const float*)d_in[2];
    const float* eavg  = (const float*)d_in[3];
    float* out = (float*)d_out;

    float* out_q    = out;
    float* out_i    = out + OFF_I;
    float* out_dist = out + OFF_DIST;
    float* out_ne   = out + OFF_NE;
    float* out_ncs  = out + OFF_NCS;
    float* out_nea  = out + OFF_NEA;

    static int gemm_grid = 0;
    if (gemm_grid == 0) {
        cudaFuncSetAttribute(gemm_kernel, cudaFuncAttributeMaxDynamicSharedMemorySize,
                             GEMM_SMEM);
        int dev = 0, sms = 148;
        cudaGetDevice(&dev);
        cudaDeviceGetAttribute(&sms, cudaDevAttrMultiProcessorCount, dev);
        gemm_grid = 2 * sms;
    }

    prep_kernel<<<T_TOK / 8 + K_CODE / 8, 256>>>(x, embed);
    gemm_kernel<<<gemm_grid, 256, GEMM_SMEM>>>(out_dist, gemm_grid);
    pass2_kernel<<<T_TOK / 8, 256>>>(x, embed, out_dist, out_q, out_i);
    finalA_kernel<<<K_CODE / 256, 256>>>(clus, out_ncs);
    finalB_kernel<<<(K_CODE * D_DIM) / 256, 256>>>(eavg, clus, out_nea, out_ne);
}

// round 12
// speedup vs baseline: 1.3887x; 1.0353x over previous
#include <cuda_runtime.h>
#include <cuda_bf16.h>
#include <cstdint>

// ---------------- problem constants ----------------
#define T_TOK  32768
#define K_CODE 8192
#define D_DIM  128
#define NTILE  64            // K_CODE / 128 column tiles
#define NTILES_TOTAL ((T_TOK / 128) * (K_CODE / 128))   // 16384
#define DECAY  0.1f
#define OMD    0.9f
#define EPSF   1e-5f

// output layout (all fp32, concatenated in reference return order)
static const size_t OFF_I    = (size_t)T_TOK * D_DIM;             // after quantized
static const size_t OFF_DIST = OFF_I + T_TOK;                     // after indices
static const size_t OFF_NE   = OFF_DIST + (size_t)T_TOK * K_CODE; // after dist
static const size_t OFF_NCS  = OFF_NE + (size_t)K_CODE * D_DIM;   // after new_embed
static const size_t OFF_NEA  = OFF_NCS + K_CODE;                  // after new_cluster_size

// ---------------- device scratch (no allocations allowed) ----------------
__device__ __align__(16) __nv_bfloat16 g_Abf[(size_t)T_TOK * D_DIM];   // 8 MB
__device__ __align__(16) __nv_bfloat16 g_Bbf[(size_t)K_CODE * D_DIM];  // 2 MB
__device__ float g_x2[T_TOK];
__device__ float g_e2[K_CODE];
__device__ unsigned long long g_tbest[(size_t)T_TOK * NTILE];          // 16 MB (fully overwritten)
__device__ float g_cs[K_CODE];
__device__ __align__(16) float g_es[(size_t)K_CODE * D_DIM];           // 4 MB
__device__ float g_S;

__device__ __forceinline__ uint32_t smem_u32(const void* p) {
    return (uint32_t)__cvta_generic_to_shared(p);
}

// ---------------- merged prep kernel (warp-per-row, float4) ----------------
__global__ void __launch_bounds__(256) prep_kernel(const float* __restrict__ x,
                                                   const float* __restrict__ embed) {
    int lane = threadIdx.x & 31;
    if (blockIdx.x == 0 && threadIdx.x == 0) g_S = 0.f;
    if (blockIdx.x < T_TOK / 8) {
        int t = blockIdx.x * 8 + (threadIdx.x >> 5);
        float4 v = *(const float4*)(x + (size_t)t * D_DIM + lane * 4);
        __nv_bfloat162 p0, p1;
        p0.x = __float2bfloat16(v.x); p0.y = __float2bfloat16(v.y);
        p1.x = __float2bfloat16(v.z); p1.y = __float2bfloat16(v.w);
        __nv_bfloat162* dst = (__nv_bfloat162*)(g_Abf + (size_t)t * D_DIM + lane * 4);
        dst[0] = p0; dst[1] = p1;
        float s = v.x * v.x + v.y * v.y + v.z * v.z + v.w * v.w;
        for (int o = 16; o; o >>= 1) s += __shfl_xor_sync(0xffffffffu, s, o);
        if (lane == 0) g_x2[t] = s;
    } else {
        int k = (blockIdx.x - T_TOK / 8) * 8 + (threadIdx.x >> 5);
        float4 v = *(const float4*)(embed + (size_t)k * D_DIM + lane * 4);
        __nv_bfloat162 p0, p1;
        p0.x = __float2bfloat16(v.x); p0.y = __float2bfloat16(v.y);
        p1.x = __float2bfloat16(v.z); p1.y = __float2bfloat16(v.w);
        __nv_bfloat162* dst = (__nv_bfloat162*)(g_Bbf + (size_t)k * D_DIM + lane * 4);
        dst[0] = p0; dst[1] = p1;
        *(float4*)(g_es + (size_t)k * D_DIM + lane * 4) = make_float4(0.f, 0.f, 0.f, 0.f);
        float s = v.x * v.x + v.y * v.y + v.z * v.z + v.w * v.w;
        for (int o = 16; o; o >>= 1) s += __shfl_xor_sync(0xffffffffu, s, o);
        if (lane == 0) { g_e2[k] = s; g_cs[k] = 0.f; }
    }
}

// ---- persistent GEMM: contiguous bm-fast tile ranges, B-resident strips ----
// tile id: bn = tile >> 8 (column strip), bm = tile & 255.  Each CTA gets a
// contiguous range -> spans <= 2 bn values -> B loaded <= 2x per CTA.
// smem: A ring 3 x 16KB @ 0;  B resident 2 slabs x 16KB @ 48K;  smin @ 80K.
// B rows PERMUTED within each 32-row span at fill time:
//   pi(s5) = (s5&16) | (((s5>>1)&3)<<2) | (((s5>>3)&1)<<1) | (s5&1)
// so accumulator fragment (nt, 2*qd+j) maps to warp-local col
//   16*(nt>>1) + 4*qd + 2*(nt&1) + j  -> each thread owns 8 CONSECUTIVE cols.
#define A_STAGE  16384
#define B_OFF    49152
#define SMIN_OFF 81920
#define GEMM_SMEM 86016

__device__ __forceinline__ void fill_A(uint32_t s_u, int t_lo, int q, int tid) {
    int tile = t_lo + (q >> 1);
    int slab = q & 1;
    int m0 = (tile & 255) * 128;
    uint32_t sA_u = s_u + (q % 3) * A_STAGE;
#pragma unroll
    for (int it = 0; it < 4; ++it) {
        int s = tid + it * 256;
        int row = s >> 3, ch = s & 7;
        uint32_t so = (uint32_t)(row * 128 + ((ch ^ (row & 7)) << 4));
        const __nv_bfloat16* ga = g_Abf + (size_t)(m0 + row) * D_DIM + slab * 64 + ch * 8;
        asm volatile("cp.async.cg.shared.global [%0], [%1], 16;" :: "r"(sA_u + so), "l"(ga));
    }
    asm volatile("cp.async.commit_group;");
}

__device__ __forceinline__ void fill_B(uint32_t s_u, int n0, int tid) {
    // both k-slabs: 2048 16B segments
#pragma unroll
    for (int it = 0; it < 8; ++it) {
        int li = tid + it * 256;
        int slab = li >> 10;
        int lr = li & 1023;
        int row = lr >> 3, ch = lr & 7;
        uint32_t so = (uint32_t)(row * 128 + ((ch ^ (row & 7)) << 4));
        int s5 = row & 31;
        int prow = (row & 96) |
                   ((s5 & 16) | (((s5 >> 1) & 3) << 2) | (((s5 >> 3) & 1) << 1) | (s5 & 1));
        const __nv_bfloat16* gb = g_Bbf + (size_t)(n0 + prow) * D_DIM + slab * 64 + ch * 8;
        asm volatile("cp.async.cg.shared.global [%0], [%1], 16;"
                     :: "r"(s_u + B_OFF + slab * A_STAGE + so), "l"(gb));
    }
    asm volatile("cp.async.commit_group;");
}

__global__ void __launch_bounds__(256, 2) gemm_kernel(float* __restrict__ dist, int grid) {
    extern __shared__ char dsm[];
    const uint32_t s_u = smem_u32(dsm);
    const int tid = threadIdx.x, lane = tid & 31, wid = tid >> 5;
    const int bid = blockIdx.x;
    const int wm = wid >> 2, wn = wid & 3;     // warps 2 (M) x 4 (N), warp tile 64x32
    const int g = lane >> 2, qd = lane & 3;
    unsigned long long* smin = (unsigned long long*)(dsm + SMIN_OFF);

    const int t_lo = (bid * NTILES_TOTAL) / grid;
    const int t_hi = ((bid + 1) * NTILES_TOTAL) / grid;
    const int Q = (t_hi - t_lo) * 2;
    int cur_bn = -1;

    // prologue: prefetch A chunks 0 and 1
    fill_A(s_u, t_lo, 0, tid);
    fill_A(s_u, t_lo, 1, tid);

    float acc[4][4][4];
#pragma unroll
    for (int a = 0; a < 4; ++a)
#pragma unroll
        for (int b = 0; b < 4; ++b)
#pragma unroll
            for (int c = 0; c < 4; ++c) acc[a][b][c] = 0.f;

#pragma unroll 1
    for (int q = 0; q < Q; ++q) {
        const int tile = t_lo + (q >> 1);
        const int bn = tile >> 8;
        if ((q & 1) == 0 && bn != cur_bn) {
            // strip boundary (<=2 per CTA): refill resident B, full drain
            __syncthreads();                    // no warp may still read old B
            fill_B(s_u, bn * 128, tid);
            asm volatile("cp.async.wait_group 0;");
            __syncthreads();
            cur_bn = bn;
        }
        if (q + 2 < Q) {
            fill_A(s_u, t_lo, q + 2, tid);
            asm volatile("cp.async.wait_group 2;");
        } else if (q + 2 == Q) {
            asm volatile("cp.async.wait_group 1;");
        } else {
            asm volatile("cp.async.wait_group 0;");
        }
        __syncthreads();

        const uint32_t sA_u = s_u + (q % 3) * A_STAGE;
        const uint32_t sB_u = s_u + B_OFF + (q & 1) * A_STAGE;
#pragma unroll
        for (int kt = 0; kt < 4; ++kt) {
            uint32_t af[4][4];
            uint32_t bfr[4][2];
#pragma unroll
            for (int mt = 0; mt < 4; ++mt) {
                int r = wm * 64 + mt * 16 + (lane & 15);
                int ch = kt * 2 + (lane >> 4);
                uint32_t ad = sA_u + (uint32_t)(r * 128 + ((ch ^ (r & 7)) << 4));
                asm volatile("ldmatrix.sync.aligned.m8n8.x4.shared.b16 {%0,%1,%2,%3}, [%4];"
                    : "=r"(af[mt][0]), "=r"(af[mt][1]), "=r"(af[mt][2]), "=r"(af[mt][3])
                    : "r"(ad));
            }
#pragma unroll
            for (int p = 0; p < 2; ++p) {
                // B n-major == col-major k x n operand -> NON-trans ldmatrix;
                // column permutation lives in smem content
                int r = wn * 32 + p * 16 + ((lane >> 4) << 3) + (lane & 7);
                int ch = kt * 2 + ((lane >> 3) & 1);
                uint32_t bd = sB_u + (uint32_t)(r * 128 + ((ch ^ (r & 7)) << 4));
                asm volatile("ldmatrix.sync.aligned.m8n8.x4.shared.b16 {%0,%1,%2,%3}, [%4];"
                    : "=r"(bfr[p * 2][0]), "=r"(bfr[p * 2][1]),
                      "=r"(bfr[p * 2 + 1][0]), "=r"(bfr[p * 2 + 1][1])
                    : "r"(bd));
            }
#pragma unroll
            for (int mt = 0; mt < 4; ++mt)
#pragma unroll
                for (int nt = 0; nt < 4; ++nt)
                    asm volatile(
                        "mma.sync.aligned.m16n8k16.row.col.f32.bf16.bf16.f32 "
                        "{%0,%1,%2,%3}, {%4,%5,%6,%7}, {%8,%9}, {%0,%1,%2,%3};"
                        : "+f"(acc[mt][nt][0]), "+f"(acc[mt][nt][1]),
                          "+f"(acc[mt][nt][2]), "+f"(acc[mt][nt][3])
                        : "r"(af[mt][0]), "r"(af[mt][1]), "r"(af[mt][2]), "r"(af[mt][3]),
                          "r"(bfr[nt][0]), "r"(bfr[nt][1]));
        }

        if (q & 1) {
            // tile complete -> epilogue (overlaps in-flight A prefetch)
            const int bnn = tile & 63;  // NOTE: bn for output indexing is tile>>8
            (void)bnn;
            const int m0 = (tile & 255) * 128;
            const int n0 = bn * 128;
            const int cb = n0 + wn * 32 + 4 * qd;
            const float4 e2a = *(const float4*)(g_e2 + cb);
            const float4 e2b = *(const float4*)(g_e2 + cb + 16);
#pragma unroll
            for (int mt = 0; mt < 4; ++mt) {
#pragma unroll
                for (int h = 0; h < 2; ++h) {
                    int lrow = wm * 64 + mt * 16 + h * 8 + g;
                    int row = m0 + lrow;
                    float x2v = g_x2[row];
                    float4 va, vb;
                    va.x = fmaf(-2.f, acc[mt][0][h * 2 + 0], x2v + e2a.x);
                    va.y = fmaf(-2.f, acc[mt][0][h * 2 + 1], x2v + e2a.y);
                    va.z = fmaf(-2.f, acc[mt][1][h * 2 + 0], x2v + e2a.z);
                    va.w = fmaf(-2.f, acc[mt][1][h * 2 + 1], x2v + e2a.w);
                    vb.x = fmaf(-2.f, acc[mt][2][h * 2 + 0], x2v + e2b.x);
                    vb.y = fmaf(-2.f, acc[mt][2][h * 2 + 1], x2v + e2b.y);
                    vb.z = fmaf(-2.f, acc[mt][3][h * 2 + 0], x2v + e2b.z);
                    vb.w = fmaf(-2.f, acc[mt][3][h * 2 + 1], x2v + e2b.w);
                    float* dr = dist + (size_t)row * K_CODE + cb;
                    asm volatile("st.global.cs.v4.f32 [%0], {%1,%2,%3,%4};"
                                 :: "l"(dr), "f"(va.x), "f"(va.y), "f"(va.z), "f"(va.w)
                                 : "memory");
                    asm volatile("st.global.cs.v4.f32 [%0], {%1,%2,%3,%4};"
                                 :: "l"(dr + 16), "f"(vb.x), "f"(vb.y), "f"(vb.z), "f"(vb.w)
                                 : "memory");
                    unsigned long long pk = ~0ull;
                    {
                        const float vv[8] = {va.x, va.y, va.z, va.w, vb.x, vb.y, vb.z, vb.w};
#pragma unroll
                        for (int j = 0; j < 8; ++j) {
                            int col = cb + (j < 4 ? j : 12 + j);
                            unsigned long long pj =
                                ((unsigned long long)__float_as_uint(vv[j]) << 32) |
                                (unsigned)col;
                            pk = pj < pk ? pj : pk;
                        }
                    }
                    unsigned long long t1 = __shfl_xor_sync(0xffffffffu, pk, 1);
                    pk = t1 < pk ? t1 : pk;
                    unsigned long long t2 = __shfl_xor_sync(0xffffffffu, pk, 2);
                    pk = t2 < pk ? t2 : pk;
                    if (qd == 0) smin[lrow * 4 + wn] = pk;
                    // reset accumulators for next tile
#pragma unroll
                    for (int nt = 0; nt < 4; ++nt) {
                        acc[mt][nt][h * 2 + 0] = 0.f;
                        acc[mt][nt][h * 2 + 1] = 0.f;
                    }
                }
            }
            __syncthreads();
            if (tid < 128) {
                unsigned long long m01 = smin[tid * 4 + 0] < smin[tid * 4 + 1]
                                       ? smin[tid * 4 + 0] : smin[tid * 4 + 1];
                unsigned long long m23 = smin[tid * 4 + 2] < smin[tid * 4 + 3]
                                       ? smin[tid * 4 + 2] : smin[tid * 4 + 3];
                g_tbest[(size_t)(m0 + tid) * NTILE + bn] = m01 < m23 ? m01 : m23;
            }
        }
        __syncthreads();   // stage (q%3) free for refill at iteration q+1
    }
}

// ---- pass2: exact fp32 argmin fixup + quantized/indices/EMA scatter ----
__global__ void __launch_bounds__(256) pass2_kernel(
    const float* __restrict__ x, const float* __restrict__ embed,
    const float* __restrict__ dist, float* __restrict__ out_q, float* __restrict__ out_i) {
    const int lane = threadIdx.x & 31;
    const int row = blockIdx.x * 8 + (threadIdx.x >> 5);

    const unsigned long long* tb = g_tbest + (size_t)row * NTILE;
    unsigned long long e0 = tb[lane], e1 = tb[lane + 32];
    unsigned long long mn = e0 < e1 ? e0 : e1;
#pragma unroll
    for (int o = 16; o; o >>= 1) {
        unsigned long long t = __shfl_xor_sync(0xffffffffu, mn, o);
        mn = t < mn ? t : mn;
    }
    const float thr = __uint_as_float((unsigned)(mn >> 32)) + 2.0f;  // b* + 2*margin

    unsigned cand0 = __ballot_sync(0xffffffffu, __uint_as_float((unsigned)(e0 >> 32)) < thr);
    unsigned cand1 = __ballot_sync(0xffffffffu, __uint_as_float((unsigned)(e1 >> 32)) < thr);

    const float4 xl4 = *(const float4*)(x + (size_t)row * D_DIM + lane * 4);
    float bestv = 3.402823466e+38f;
    int bestc = 0x7fffffff;

#pragma unroll 1
    for (int grp = 0; grp < 2; ++grp) {
        unsigned cm = grp ? cand1 : cand0;
        while (cm) {
            int t = __ffs(cm) - 1;
            cm &= cm - 1;
            int tile = grp * 32 + t;
            float4 dv = *(const float4*)(dist + (size_t)row * K_CODE + tile * 128 + lane * 4);
            float dvv[4] = {dv.x, dv.y, dv.z, dv.w};
#pragma unroll
            for (int j = 0; j < 4; ++j) {
                unsigned mask = __ballot_sync(0xffffffffu, dvv[j] < thr);
                while (mask) {
                    int l = __ffs(mask) - 1;
                    mask &= mask - 1;
                    int col = tile * 128 + l * 4 + j;
                    float4 ev = *(const float4*)(embed + (size_t)col * D_DIM + lane * 4);
                    float d0 = xl4.x - ev.x, d1 = xl4.y - ev.y;
                    float d2 = xl4.z - ev.z, d3 = xl4.w - ev.w;
                    float s = d0 * d0 + d1 * d1 + d2 * d2 + d3 * d3;
#pragma unroll
                    for (int o = 16; o; o >>= 1) s += __shfl_xor_sync(0xffffffffu, s, o);
                    if (s < bestv || (s == bestv && col < bestc)) { bestv = s; bestc = col; }
                }
            }
        }
    }

    if (lane == 0) {
        out_i[row] = (float)bestc;
        atomicAdd(&g_cs[bestc], 1.0f);
    }
    float4 ev = *(const float4*)(embed + (size_t)bestc * D_DIM + lane * 4);
    *(float4*)(out_q + (size_t)row * D_DIM + lane * 4) = ev;
    float* esr = g_es + (size_t)bestc * D_DIM + lane * 4;
    atomicAdd(esr + 0, xl4.x);
    atomicAdd(esr + 1, xl4.y);
    atomicAdd(esr + 2, xl4.z);
    atomicAdd(esr + 3, xl4.w);
}

// multi-block: ncs write + global sum via atomics (g_S zeroed in prep)
__global__ void __launch_bounds__(256) finalA_kernel(const float* __restrict__ clus,
                                                     float* __restrict__ out_ncs) {
    int k = blockIdx.x * 256 + threadIdx.x;
    int lane = threadIdx.x & 31, wid = threadIdx.x >> 5;
    float v = DECAY * clus[k] + OMD * g_cs[k];
    out_ncs[k] = v;
    float s = v;
    for (int o = 16; o; o >>= 1) s += __shfl_xor_sync(0xffffffffu, s, o);
    __shared__ float sred[8];
    if (lane == 0) sred[wid] = s;
    __syncthreads();
    if (threadIdx.x == 0) {
        float b = sred[0] + sred[1] + sred[2] + sred[3]
                + sred[4] + sred[5] + sred[6] + sred[7];
        atomicAdd(&g_S, b);
    }
}

__global__ void finalB_kernel(const float* __restrict__ eavg, const float* __restrict__ clus,
                              float* __restrict__ out_nea, float* __restrict__ out_ne) {
    int i = blockIdx.x * blockDim.x + threadIdx.x;   // 0 .. K*D-1
    int k = i >> 7;
    float nea = DECAY * eavg[i] + OMD * g_es[i];
    out_nea[i] = nea;
    float ncs = DECAY * clus[k] + OMD * g_cs[k];
    float norm = (ncs + EPSF) / (g_S + (float)K_CODE * EPSF);
    out_ne[i] = nea / norm;
}

// ---------------- launch ----------------
extern "C" void kernel_launch(void* const* d_in, const int* in_sizes, int n_in,
                              void* d_out, int out_size) {
    (void)in_sizes; (void)n_in; (void)out_size;
    const float* x     = (const float*)d_in[0];
    const float* embed = (const float*)d_in[1];
    const float* clus  = (const float*)d_in[2];
    const float* eavg  = (const float*)d_in[3];
    float* out = (float*)d_out;

    float* out_q    = out;
    float* out_i    = out + OFF_I;
    float* out_dist = out + OFF_DIST;
    float* out_ne   = out + OFF_NE;
    float* out_ncs  = out + OFF_NCS;
    float* out_nea  = out + OFF_NEA;

    static int gemm_grid = 0;
    if (gemm_grid == 0) {
        cudaFuncSetAttribute(gemm_kernel, cudaFuncAttributeMaxDynamicSharedMemorySize,
                             GEMM_SMEM);
        int dev = 0, sms = 148;
        cudaGetDevice(&dev);
        cudaDeviceGetAttribute(&sms, cudaDevAttrMultiProcessorCount, dev);
        gemm_grid = 2 * sms;
    }

    prep_kernel<<<T_TOK / 8 + K_CODE / 8, 256>>>(x, embed);
    gemm_kernel<<<gemm_grid, 256, GEMM_SMEM>>>(out_dist, gemm_grid);
    pass2_kernel<<<T_TOK / 8, 256>>>(x, embed, out_dist, out_q, out_i);
    finalA_kernel<<<K_CODE / 256, 256>>>(clus, out_ncs);
    finalB_kernel<<<(K_CODE * D_DIM) / 256, 256>>>(eavg, clus, out_nea, out_ne);
}

// round 13
// speedup vs baseline: 1.5257x; 1.0987x over previous
#include <cuda_runtime.h>
#include <cuda_bf16.h>
#include <cstdint>

// ---------------- problem constants ----------------
#define T_TOK  32768
#define K_CODE 8192
#define D_DIM  128
#define NTILE  64            // K_CODE / 128 column tiles
#define NTILES_TOTAL ((T_TOK / 128) * (K_CODE / 128))   // 16384
#define DECAY  0.1f
#define OMD    0.9f
#define EPSF   1e-5f

// output layout (all fp32, concatenated in reference return order)
static const size_t OFF_I    = (size_t)T_TOK * D_DIM;             // after quantized
static const size_t OFF_DIST = OFF_I + T_TOK;                     // after indices
static const size_t OFF_NE   = OFF_DIST + (size_t)T_TOK * K_CODE; // after dist
static const size_t OFF_NCS  = OFF_NE + (size_t)K_CODE * D_DIM;   // after new_embed
static const size_t OFF_NEA  = OFF_NCS + K_CODE;                  // after new_cluster_size

// ---------------- device scratch (no allocations allowed) ----------------
__device__ __align__(16) __nv_bfloat16 g_Abf[(size_t)T_TOK * D_DIM];   // 8 MB
__device__ __align__(16) __nv_bfloat16 g_Bbf[(size_t)K_CODE * D_DIM];  // 2 MB
__device__ float g_x2[T_TOK];
__device__ float g_e2[K_CODE];
__device__ float g_tbestf[(size_t)T_TOK * NTILE];                      // 8 MB (fully overwritten)
__device__ float g_cs[K_CODE];
__device__ __align__(16) float g_es[(size_t)K_CODE * D_DIM];           // 4 MB
__device__ float g_S;

__device__ __forceinline__ uint32_t smem_u32(const void* p) {
    return (uint32_t)__cvta_generic_to_shared(p);
}

// ---------------- merged prep kernel (warp-per-row, float4) ----------------
__global__ void __launch_bounds__(256) prep_kernel(const float* __restrict__ x,
                                                   const float* __restrict__ embed) {
    int lane = threadIdx.x & 31;
    if (blockIdx.x == 0 && threadIdx.x == 0) g_S = 0.f;
    if (blockIdx.x < T_TOK / 8) {
        int t = blockIdx.x * 8 + (threadIdx.x >> 5);
        float4 v = *(const float4*)(x + (size_t)t * D_DIM + lane * 4);
        __nv_bfloat162 p0, p1;
        p0.x = __float2bfloat16(v.x); p0.y = __float2bfloat16(v.y);
        p1.x = __float2bfloat16(v.z); p1.y = __float2bfloat16(v.w);
        __nv_bfloat162* dst = (__nv_bfloat162*)(g_Abf + (size_t)t * D_DIM + lane * 4);
        dst[0] = p0; dst[1] = p1;
        float s = v.x * v.x + v.y * v.y + v.z * v.z + v.w * v.w;
        for (int o = 16; o; o >>= 1) s += __shfl_xor_sync(0xffffffffu, s, o);
        if (lane == 0) g_x2[t] = s;
    } else {
        int k = (blockIdx.x - T_TOK / 8) * 8 + (threadIdx.x >> 5);
        float4 v = *(const float4*)(embed + (size_t)k * D_DIM + lane * 4);
        __nv_bfloat162 p0, p1;
        p0.x = __float2bfloat16(v.x); p0.y = __float2bfloat16(v.y);
        p1.x = __float2bfloat16(v.z); p1.y = __float2bfloat16(v.w);
        __nv_bfloat162* dst = (__nv_bfloat162*)(g_Bbf + (size_t)k * D_DIM + lane * 4);
        dst[0] = p0; dst[1] = p1;
        *(float4*)(g_es + (size_t)k * D_DIM + lane * 4) = make_float4(0.f, 0.f, 0.f, 0.f);
        float s = v.x * v.x + v.y * v.y + v.z * v.z + v.w * v.w;
        for (int o = 16; o; o >>= 1) s += __shfl_xor_sync(0xffffffffu, s, o);
        if (lane == 0) { g_e2[k] = s; g_cs[k] = 0.f; }
    }
}

// ---- persistent GEMM: contiguous bm-fast tile ranges, B-resident strips ----
// tile id: bn = tile >> 8 (column strip), bm = tile & 255.  Each CTA gets a
// contiguous range -> spans <= 2 bn values -> B loaded <= 2x per CTA.
// smem: A ring 3 x 16KB @ 0;  B resident 2 slabs x 16KB @ 48K;  sminf @ 80K.
// B rows PERMUTED within each 32-row span at fill time:
//   pi(s5) = (s5&16) | (((s5>>1)&3)<<2) | (((s5>>3)&1)<<1) | (s5&1)
// so accumulator fragment (nt, 2*qd+j) maps to warp-local col
//   16*(nt>>1) + 4*qd + 2*(nt&1) + j  -> each thread owns 8 CONSECUTIVE cols.
#define A_STAGE  16384
#define B_OFF    49152
#define SMIN_OFF 81920
#define GEMM_SMEM 84480

__device__ __forceinline__ void fill_A(uint32_t s_u, int t_lo, int q, int tid) {
    int tile = t_lo + (q >> 1);
    int slab = q & 1;
    int m0 = (tile & 255) * 128;
    uint32_t sA_u = s_u + (q % 3) * A_STAGE;
#pragma unroll
    for (int it = 0; it < 4; ++it) {
        int s = tid + it * 256;
        int row = s >> 3, ch = s & 7;
        uint32_t so = (uint32_t)(row * 128 + ((ch ^ (row & 7)) << 4));
        const __nv_bfloat16* ga = g_Abf + (size_t)(m0 + row) * D_DIM + slab * 64 + ch * 8;
        asm volatile("cp.async.cg.shared.global [%0], [%1], 16;" :: "r"(sA_u + so), "l"(ga));
    }
    asm volatile("cp.async.commit_group;");
}

__device__ __forceinline__ void fill_B(uint32_t s_u, int n0, int tid) {
    // both k-slabs: 2048 16B segments
#pragma unroll
    for (int it = 0; it < 8; ++it) {
        int li = tid + it * 256;
        int slab = li >> 10;
        int lr = li & 1023;
        int row = lr >> 3, ch = lr & 7;
        uint32_t so = (uint32_t)(row * 128 + ((ch ^ (row & 7)) << 4));
        int s5 = row & 31;
        int prow = (row & 96) |
                   ((s5 & 16) | (((s5 >> 1) & 3) << 2) | (((s5 >> 3) & 1) << 1) | (s5 & 1));
        const __nv_bfloat16* gb = g_Bbf + (size_t)(n0 + prow) * D_DIM + slab * 64 + ch * 8;
        asm volatile("cp.async.cg.shared.global [%0], [%1], 16;"
                     :: "r"(s_u + B_OFF + slab * A_STAGE + so), "l"(gb));
    }
    asm volatile("cp.async.commit_group;");
}

__global__ void __launch_bounds__(256, 2) gemm_kernel(float* __restrict__ dist, int grid) {
    extern __shared__ char dsm[];
    const uint32_t s_u = smem_u32(dsm);
    const int tid = threadIdx.x, lane = tid & 31, wid = tid >> 5;
    const int bid = blockIdx.x;
    const int wm = wid >> 2, wn = wid & 3;     // warps 2 (M) x 4 (N), warp tile 64x32
    const int g = lane >> 2, qd = lane & 3;
    float* sminf = (float*)(dsm + SMIN_OFF);

    const int t_lo = (bid * NTILES_TOTAL) / grid;
    const int t_hi = ((bid + 1) * NTILES_TOTAL) / grid;
    const int Q = (t_hi - t_lo) * 2;
    int cur_bn = -1;

    // prologue: prefetch A chunks 0 and 1
    fill_A(s_u, t_lo, 0, tid);
    fill_A(s_u, t_lo, 1, tid);

    float acc[4][4][4];
#pragma unroll
    for (int a = 0; a < 4; ++a)
#pragma unroll
        for (int b = 0; b < 4; ++b)
#pragma unroll
            for (int c = 0; c < 4; ++c) acc[a][b][c] = 0.f;

#pragma unroll 1
    for (int q = 0; q < Q; ++q) {
        const int tile = t_lo + (q >> 1);
        const int bn = tile >> 8;
        if ((q & 1) == 0 && bn != cur_bn) {
            // strip boundary (<=2 per CTA): refill resident B, full drain
            __syncthreads();                    // no warp may still read old B
            fill_B(s_u, bn * 128, tid);
            asm volatile("cp.async.wait_group 0;");
            __syncthreads();
            cur_bn = bn;
        }
        if (q + 2 < Q) {
            fill_A(s_u, t_lo, q + 2, tid);
            asm volatile("cp.async.wait_group 2;");
        } else if (q + 2 == Q) {
            asm volatile("cp.async.wait_group 1;");
        } else {
            asm volatile("cp.async.wait_group 0;");
        }
        __syncthreads();

        const uint32_t sA_u = s_u + (q % 3) * A_STAGE;
        const uint32_t sB_u = s_u + B_OFF + (q & 1) * A_STAGE;
#pragma unroll
        for (int kt = 0; kt < 4; ++kt) {
            uint32_t af[4][4];
            uint32_t bfr[4][2];
#pragma unroll
            for (int mt = 0; mt < 4; ++mt) {
                int r = wm * 64 + mt * 16 + (lane & 15);
                int ch = kt * 2 + (lane >> 4);
                uint32_t ad = sA_u + (uint32_t)(r * 128 + ((ch ^ (r & 7)) << 4));
                asm volatile("ldmatrix.sync.aligned.m8n8.x4.shared.b16 {%0,%1,%2,%3}, [%4];"
                    : "=r"(af[mt][0]), "=r"(af[mt][1]), "=r"(af[mt][2]), "=r"(af[mt][3])
                    : "r"(ad));
            }
#pragma unroll
            for (int p = 0; p < 2; ++p) {
                // B n-major == col-major k x n operand -> NON-trans ldmatrix;
                // column permutation lives in smem content
                int r = wn * 32 + p * 16 + ((lane >> 4) << 3) + (lane & 7);
                int ch = kt * 2 + ((lane >> 3) & 1);
                uint32_t bd = sB_u + (uint32_t)(r * 128 + ((ch ^ (r & 7)) << 4));
                asm volatile("ldmatrix.sync.aligned.m8n8.x4.shared.b16 {%0,%1,%2,%3}, [%4];"
                    : "=r"(bfr[p * 2][0]), "=r"(bfr[p * 2][1]),
                      "=r"(bfr[p * 2 + 1][0]), "=r"(bfr[p * 2 + 1][1])
                    : "r"(bd));
            }
#pragma unroll
            for (int mt = 0; mt < 4; ++mt)
#pragma unroll
                for (int nt = 0; nt < 4; ++nt)
                    asm volatile(
                        "mma.sync.aligned.m16n8k16.row.col.f32.bf16.bf16.f32 "
                        "{%0,%1,%2,%3}, {%4,%5,%6,%7}, {%8,%9}, {%0,%1,%2,%3};"
                        : "+f"(acc[mt][nt][0]), "+f"(acc[mt][nt][1]),
                          "+f"(acc[mt][nt][2]), "+f"(acc[mt][nt][3])
                        : "r"(af[mt][0]), "r"(af[mt][1]), "r"(af[mt][2]), "r"(af[mt][3]),
                          "r"(bfr[nt][0]), "r"(bfr[nt][1]));
        }

        if (q & 1) {
            // tile complete -> epilogue (overlaps in-flight A prefetch).
            // g_tbestf tracks only the float tile-min: pass2 re-derives the
            // argmin index exactly by re-scanning candidate tiles in dist.
            const int m0 = (tile & 255) * 128;
            const int n0 = bn * 128;
            const int cb = n0 + wn * 32 + 4 * qd;
            const float4 e2a = *(const float4*)(g_e2 + cb);
            const float4 e2b = *(const float4*)(g_e2 + cb + 16);
#pragma unroll
            for (int mt = 0; mt < 4; ++mt) {
#pragma unroll
                for (int h = 0; h < 2; ++h) {
                    int lrow = wm * 64 + mt * 16 + h * 8 + g;
                    int row = m0 + lrow;
                    float x2v = g_x2[row];
                    float4 va, vb;
                    va.x = fmaf(-2.f, acc[mt][0][h * 2 + 0], x2v + e2a.x);
                    va.y = fmaf(-2.f, acc[mt][0][h * 2 + 1], x2v + e2a.y);
                    va.z = fmaf(-2.f, acc[mt][1][h * 2 + 0], x2v + e2a.z);
                    va.w = fmaf(-2.f, acc[mt][1][h * 2 + 1], x2v + e2a.w);
                    vb.x = fmaf(-2.f, acc[mt][2][h * 2 + 0], x2v + e2b.x);
                    vb.y = fmaf(-2.f, acc[mt][2][h * 2 + 1], x2v + e2b.y);
                    vb.z = fmaf(-2.f, acc[mt][3][h * 2 + 0], x2v + e2b.z);
                    vb.w = fmaf(-2.f, acc[mt][3][h * 2 + 1], x2v + e2b.w);
                    float* dr = dist + (size_t)row * K_CODE + cb;
                    asm volatile("st.global.cs.v4.f32 [%0], {%1,%2,%3,%4};"
                                 :: "l"(dr), "f"(va.x), "f"(va.y), "f"(va.z), "f"(va.w)
                                 : "memory");
                    asm volatile("st.global.cs.v4.f32 [%0], {%1,%2,%3,%4};"
                                 :: "l"(dr + 16), "f"(vb.x), "f"(vb.y), "f"(vb.z), "f"(vb.w)
                                 : "memory");
                    float m8 = fminf(fminf(fminf(va.x, va.y), fminf(va.z, va.w)),
                                     fminf(fminf(vb.x, vb.y), fminf(vb.z, vb.w)));
                    m8 = fminf(m8, __shfl_xor_sync(0xffffffffu, m8, 1));
                    m8 = fminf(m8, __shfl_xor_sync(0xffffffffu, m8, 2));
                    if (qd == 0) sminf[lrow * 4 + wn] = m8;
                    // reset accumulators for next tile
#pragma unroll
                    for (int nt = 0; nt < 4; ++nt) {
                        acc[mt][nt][h * 2 + 0] = 0.f;
                        acc[mt][nt][h * 2 + 1] = 0.f;
                    }
                }
            }
            __syncthreads();
            if (tid < 128) {
                float m01 = fminf(sminf[tid * 4 + 0], sminf[tid * 4 + 1]);
                float m23 = fminf(sminf[tid * 4 + 2], sminf[tid * 4 + 3]);
                g_tbestf[(size_t)(m0 + tid) * NTILE + bn] = fminf(m01, m23);
            }
        }
        __syncthreads();   // stage (q%3) free for refill at iteration q+1
    }
}

// ---- pass2: exact fp32 argmin fixup + quantized/indices/EMA scatter ----
__global__ void __launch_bounds__(256) pass2_kernel(
    const float* __restrict__ x, const float* __restrict__ embed,
    const float* __restrict__ dist, float* __restrict__ out_q, float* __restrict__ out_i) {
    const int lane = threadIdx.x & 31;
    const int row = blockIdx.x * 8 + (threadIdx.x >> 5);

    const float* tb = g_tbestf + (size_t)row * NTILE;
    float e0 = tb[lane], e1 = tb[lane + 32];
    float mn = fminf(e0, e1);
#pragma unroll
    for (int o = 16; o; o >>= 1) mn = fminf(mn, __shfl_xor_sync(0xffffffffu, mn, o));
    const float thr = mn + 2.0f;  // b* + 2*margin

    unsigned cand0 = __ballot_sync(0xffffffffu, e0 < thr);
    unsigned cand1 = __ballot_sync(0xffffffffu, e1 < thr);

    const float4 xl4 = *(const float4*)(x + (size_t)row * D_DIM + lane * 4);
    float bestv = 3.402823466e+38f;
    int bestc = 0x7fffffff;

#pragma unroll 1
    for (int grp = 0; grp < 2; ++grp) {
        unsigned cm = grp ? cand1 : cand0;
        while (cm) {
            int t = __ffs(cm) - 1;
            cm &= cm - 1;
            int tile = grp * 32 + t;
            float4 dv = *(const float4*)(dist + (size_t)row * K_CODE + tile * 128 + lane * 4);
            float dvv[4] = {dv.x, dv.y, dv.z, dv.w};
#pragma unroll
            for (int j = 0; j < 4; ++j) {
                unsigned mask = __ballot_sync(0xffffffffu, dvv[j] < thr);
                while (mask) {
                    int l = __ffs(mask) - 1;
                    mask &= mask - 1;
                    int col = tile * 128 + l * 4 + j;
                    float4 ev = *(const float4*)(embed + (size_t)col * D_DIM + lane * 4);
                    float d0 = xl4.x - ev.x, d1 = xl4.y - ev.y;
                    float d2 = xl4.z - ev.z, d3 = xl4.w - ev.w;
                    float s = d0 * d0 + d1 * d1 + d2 * d2 + d3 * d3;
#pragma unroll
                    for (int o = 16; o; o >>= 1) s += __shfl_xor_sync(0xffffffffu, s, o);
                    if (s < bestv || (s == bestv && col < bestc)) { bestv = s; bestc = col; }
                }
            }
        }
    }

    if (lane == 0) {
        out_i[row] = (float)bestc;
        atomicAdd(&g_cs[bestc], 1.0f);
    }
    float4 ev = *(const float4*)(embed + (size_t)bestc * D_DIM + lane * 4);
    *(float4*)(out_q + (size_t)row * D_DIM + lane * 4) = ev;
    float* esr = g_es + (size_t)bestc * D_DIM + lane * 4;
    atomicAdd(esr + 0, xl4.x);
    atomicAdd(esr + 1, xl4.y);
    atomicAdd(esr + 2, xl4.z);
    atomicAdd(esr + 3, xl4.w);
}

// multi-block: ncs write + global sum via atomics (g_S zeroed in prep)
__global__ void __launch_bounds__(256) finalA_kernel(const float* __restrict__ clus,
                                                     float* __restrict__ out_ncs) {
    int k = blockIdx.x * 256 + threadIdx.x;
    int lane = threadIdx.x & 31, wid = threadIdx.x >> 5;
    float v = DECAY * clus[k] + OMD * g_cs[k];
    out_ncs[k] = v;
    float s = v;
    for (int o = 16; o; o >>= 1) s += __shfl_xor_sync(0xffffffffu, s, o);
    __shared__ float sred[8];
    if (lane == 0) sred[wid] = s;
    __syncthreads();
    if (threadIdx.x == 0) {
        float b = sred[0] + sred[1] + sred[2] + sred[3]
                + sred[4] + sred[5] + sred[6] + sred[7];
        atomicAdd(&g_S, b);
    }
}

__global__ void finalB_kernel(const float* __restrict__ eavg, const float* __restrict__ clus,
                              float* __restrict__ out_nea, float* __restrict__ out_ne) {
    int i = blockIdx.x * blockDim.x + threadIdx.x;   // 0 .. K*D-1
    int k = i >> 7;
    float nea = DECAY * eavg[i] + OMD * g_es[i];
    out_nea[i] = nea;
    float ncs = DECAY * clus[k] + OMD * g_cs[k];
    float norm = (ncs + EPSF) / (g_S + (float)K_CODE * EPSF);
    out_ne[i] = nea / norm;
}

// ---------------- launch ----------------
extern "C" void kernel_launch(void* const* d_in, const int* in_sizes, int n_in,
                              void* d_out, int out_size) {
    (void)in_sizes; (void)n_in; (void)out_size;
    const float* x     = (const float*)d_in[0];
    const float* embed = (const float*)d_in[1];
    const float* clus  = (const float*)d_in[2];
    const float* eavg  = (const float*)d_in[3];
    float* out = (float*)d_out;

    float* out_q    = out;
    float* out_i    = out + OFF_I;
    float* out_dist = out + OFF_DIST;
    float* out_ne   = out + OFF_NE;
    float* out_ncs  = out + OFF_NCS;
    float* out_nea  = out + OFF_NEA;

    static int gemm_grid = 0;
    if (gemm_grid == 0) {
        cudaFuncSetAttribute(gemm_kernel, cudaFuncAttributeMaxDynamicSharedMemorySize,
                             GEMM_SMEM);
        int dev = 0, sms = 148;
        cudaGetDevice(&dev);
        cudaDeviceGetAttribute(&sms, cudaDevAttrMultiProcessorCount, dev);
        gemm_grid = 2 * sms;
    }

    prep_kernel<<<T_TOK / 8 + K_CODE / 8, 256>>>(x, embed);
    gemm_kernel<<<gemm_grid, 256, GEMM_SMEM>>>(out_dist, gemm_grid);
    pass2_kernel<<<T_TOK / 8, 256>>>(x, embed, out_dist, out_q, out_i);
    finalA_kernel<<<K_CODE / 256, 256>>>(clus, out_ncs);
    finalB_kernel<<<(K_CODE * D_DIM) / 256, 256>>>(eavg, clus, out_nea, out_ne);
}

// round 14
// speedup vs baseline: 1.5665x; 1.0267x over previous
#include <cuda_runtime.h>
#include <cuda_bf16.h>
#include <cstdint>

// ---------------- problem constants ----------------
#define T_TOK  32768
#define K_CODE 8192
#define D_DIM  128
#define NTILE  64            // K_CODE / 128 column tiles
#define NTILES_TOTAL ((T_TOK / 128) * (K_CODE / 128))   // 16384
#define DECAY  0.1f
#define OMD    0.9f
#define EPSF   1e-5f

// output layout (all fp32, concatenated in reference return order)
static const size_t OFF_I    = (size_t)T_TOK * D_DIM;             // after quantized
static const size_t OFF_DIST = OFF_I + T_TOK;                     // after indices
static const size_t OFF_NE   = OFF_DIST + (size_t)T_TOK * K_CODE; // after dist
static const size_t OFF_NCS  = OFF_NE + (size_t)K_CODE * D_DIM;   // after new_embed
static const size_t OFF_NEA  = OFF_NCS + K_CODE;                  // after new_cluster_size

// ---------------- device scratch (no allocations allowed) ----------------
__device__ __align__(16) __nv_bfloat16 g_Abf[(size_t)T_TOK * D_DIM];   // 8 MB
__device__ __align__(16) __nv_bfloat16 g_Bbf[(size_t)K_CODE * D_DIM];  // 2 MB
__device__ float g_x2[T_TOK];
__device__ float g_e2[K_CODE];
__device__ float g_tbestf[(size_t)T_TOK * NTILE];                      // 8 MB (fully overwritten)
__device__ float g_cs[K_CODE];
__device__ __align__(16) float g_es[(size_t)K_CODE * D_DIM];           // 4 MB
__device__ float g_S;

__device__ __forceinline__ uint32_t smem_u32(const void* p) {
    return (uint32_t)__cvta_generic_to_shared(p);
}

// ---------------- merged prep kernel (warp-per-row, float4) ----------------
__global__ void __launch_bounds__(256) prep_kernel(const float* __restrict__ x,
                                                   const float* __restrict__ embed) {
    int lane = threadIdx.x & 31;
    if (blockIdx.x == 0 && threadIdx.x == 0) g_S = 0.f;
    if (blockIdx.x < T_TOK / 8) {
        int t = blockIdx.x * 8 + (threadIdx.x >> 5);
        float4 v = *(const float4*)(x + (size_t)t * D_DIM + lane * 4);
        __nv_bfloat162 p0, p1;
        p0.x = __float2bfloat16(v.x); p0.y = __float2bfloat16(v.y);
        p1.x = __float2bfloat16(v.z); p1.y = __float2bfloat16(v.w);
        __nv_bfloat162* dst = (__nv_bfloat162*)(g_Abf + (size_t)t * D_DIM + lane * 4);
        dst[0] = p0; dst[1] = p1;
        float s = v.x * v.x + v.y * v.y + v.z * v.z + v.w * v.w;
        for (int o = 16; o; o >>= 1) s += __shfl_xor_sync(0xffffffffu, s, o);
        if (lane == 0) g_x2[t] = s;
    } else {
        int k = (blockIdx.x - T_TOK / 8) * 8 + (threadIdx.x >> 5);
        float4 v = *(const float4*)(embed + (size_t)k * D_DIM + lane * 4);
        __nv_bfloat162 p0, p1;
        p0.x = __float2bfloat16(v.x); p0.y = __float2bfloat16(v.y);
        p1.x = __float2bfloat16(v.z); p1.y = __float2bfloat16(v.w);
        __nv_bfloat162* dst = (__nv_bfloat162*)(g_Bbf + (size_t)k * D_DIM + lane * 4);
        dst[0] = p0; dst[1] = p1;
        *(float4*)(g_es + (size_t)k * D_DIM + lane * 4) = make_float4(0.f, 0.f, 0.f, 0.f);
        float s = v.x * v.x + v.y * v.y + v.z * v.z + v.w * v.w;
        for (int o = 16; o; o >>= 1) s += __shfl_xor_sync(0xffffffffu, s, o);
        if (lane == 0) { g_e2[k] = s; g_cs[k] = 0.f; }
    }
}

// ---- persistent GEMM: full-K A stages (2-ring), B-resident strips ----
// tile id: bn = tile >> 8 (column strip), bm = tile & 255.  Contiguous per-CTA
// tile ranges -> <= 2 bn values -> B loaded <= 2x per CTA.
// smem: A ring 2 x 32KB @ 0 (each: slab0 @ +0, slab1 @ +16K);
//       B resident 2 slabs x 16KB @ 64K;  sminf @ 96K.
// B rows PERMUTED within each 32-row span at fill time:
//   pi(s5) = (s5&16) | (((s5>>1)&3)<<2) | (((s5>>3)&1)<<1) | (s5&1)
// so accumulator fragment (nt, 2*qd+j) maps to warp-local col
//   16*(nt>>1) + 4*qd + 2*(nt&1) + j  -> each thread owns 8 CONSECUTIVE cols.
#define A_STAGE  32768
#define B_SLAB   16384
#define B_OFF    65536
#define SMIN_OFF 98304
#define GEMM_SMEM 100352

__device__ __forceinline__ void fill_A(uint32_t s_u, int tile, int stage, int tid) {
    int m0 = (tile & 255) * 128;
    uint32_t sA_u = s_u + stage * A_STAGE;
    // full K=128: 2 slabs x 1024 16B segments
#pragma unroll
    for (int it = 0; it < 8; ++it) {
        int li = tid + it * 256;
        int slab = li >> 10;
        int lr = li & 1023;
        int row = lr >> 3, ch = lr & 7;
        uint32_t so = (uint32_t)(row * 128 + ((ch ^ (row & 7)) << 4));
        const __nv_bfloat16* ga = g_Abf + (size_t)(m0 + row) * D_DIM + slab * 64 + ch * 8;
        asm volatile("cp.async.cg.shared.global [%0], [%1], 16;"
                     :: "r"(sA_u + slab * B_SLAB + so), "l"(ga));
    }
    asm volatile("cp.async.commit_group;");
}

__device__ __forceinline__ void fill_B(uint32_t s_u, int n0, int tid) {
    // both k-slabs: 2048 16B segments
#pragma unroll
    for (int it = 0; it < 8; ++it) {
        int li = tid + it * 256;
        int slab = li >> 10;
        int lr = li & 1023;
        int row = lr >> 3, ch = lr & 7;
        uint32_t so = (uint32_t)(row * 128 + ((ch ^ (row & 7)) << 4));
        int s5 = row & 31;
        int prow = (row & 96) |
                   ((s5 & 16) | (((s5 >> 1) & 3) << 2) | (((s5 >> 3) & 1) << 1) | (s5 & 1));
        const __nv_bfloat16* gb = g_Bbf + (size_t)(n0 + prow) * D_DIM + slab * 64 + ch * 8;
        asm volatile("cp.async.cg.shared.global [%0], [%1], 16;"
                     :: "r"(s_u + B_OFF + slab * B_SLAB + so), "l"(gb));
    }
    asm volatile("cp.async.commit_group;");
}

__global__ void __launch_bounds__(256, 2) gemm_kernel(float* __restrict__ dist, int grid) {
    extern __shared__ char dsm[];
    const uint32_t s_u = smem_u32(dsm);
    const int tid = threadIdx.x, lane = tid & 31, wid = tid >> 5;
    const int bid = blockIdx.x;
    const int wm = wid >> 2, wn = wid & 3;     // warps 2 (M) x 4 (N), warp tile 64x32
    const int g = lane >> 2, qd = lane & 3;
    float* sminf = (float*)(dsm + SMIN_OFF);

    const int t_lo = (bid * NTILES_TOTAL) / grid;
    const int t_hi = ((bid + 1) * NTILES_TOTAL) / grid;
    const int nT = t_hi - t_lo;
    int cur_bn = t_lo >> 8;

    // prologue: resident B for first strip, then A for first tile
    fill_B(s_u, cur_bn * 128, tid);
    fill_A(s_u, t_lo, 0, tid);

    float acc[4][4][4];
#pragma unroll
    for (int a = 0; a < 4; ++a)
#pragma unroll
        for (int b = 0; b < 4; ++b)
#pragma unroll
            for (int c = 0; c < 4; ++c) acc[a][b][c] = 0.f;

#pragma unroll 1
    for (int it = 0; it < nT; ++it) {
        const int tile = t_lo + it;
        const int bn = tile >> 8;
        if (bn != cur_bn) {
            // strip boundary: all compute on old B finished at previous tile's
            // epilogue sync, so the refill can be issued directly.
            fill_B(s_u, bn * 128, tid);
            cur_bn = bn;
        }
        if (it + 1 < nT) {
            // prefetch next tile's A into the other stage (its previous readers
            // finished before this thread passed the last epilogue sync)
            fill_A(s_u, tile + 1, (it + 1) & 1, tid);
            asm volatile("cp.async.wait_group 1;");   // drains A(it) (+ B if any)
        } else {
            asm volatile("cp.async.wait_group 0;");
        }
        __syncthreads();

        const uint32_t stage_u = s_u + (it & 1) * A_STAGE;
#pragma unroll
        for (int slab = 0; slab < 2; ++slab) {
            const uint32_t sA_u = stage_u + slab * B_SLAB;
            const uint32_t sB_u = s_u + B_OFF + slab * B_SLAB;
#pragma unroll
            for (int kt = 0; kt < 4; ++kt) {
                uint32_t af[4][4];
                uint32_t bfr[4][2];
#pragma unroll
                for (int mt = 0; mt < 4; ++mt) {
                    int r = wm * 64 + mt * 16 + (lane & 15);
                    int ch = kt * 2 + (lane >> 4);
                    uint32_t ad = sA_u + (uint32_t)(r * 128 + ((ch ^ (r & 7)) << 4));
                    asm volatile(
                        "ldmatrix.sync.aligned.m8n8.x4.shared.b16 {%0,%1,%2,%3}, [%4];"
                        : "=r"(af[mt][0]), "=r"(af[mt][1]), "=r"(af[mt][2]), "=r"(af[mt][3])
                        : "r"(ad));
                }
#pragma unroll
                for (int p = 0; p < 2; ++p) {
                    // B n-major == col-major k x n operand -> NON-trans ldmatrix;
                    // column permutation lives in smem content
                    int r = wn * 32 + p * 16 + ((lane >> 4) << 3) + (lane & 7);
                    int ch = kt * 2 + ((lane >> 3) & 1);
                    uint32_t bd = sB_u + (uint32_t)(r * 128 + ((ch ^ (r & 7)) << 4));
                    asm volatile(
                        "ldmatrix.sync.aligned.m8n8.x4.shared.b16 {%0,%1,%2,%3}, [%4];"
                        : "=r"(bfr[p * 2][0]), "=r"(bfr[p * 2][1]),
                          "=r"(bfr[p * 2 + 1][0]), "=r"(bfr[p * 2 + 1][1])
                        : "r"(bd));
                }
#pragma unroll
                for (int mt = 0; mt < 4; ++mt)
#pragma unroll
                    for (int nt = 0; nt < 4; ++nt)
                        asm volatile(
                            "mma.sync.aligned.m16n8k16.row.col.f32.bf16.bf16.f32 "
                            "{%0,%1,%2,%3}, {%4,%5,%6,%7}, {%8,%9}, {%0,%1,%2,%3};"
                            : "+f"(acc[mt][nt][0]), "+f"(acc[mt][nt][1]),
                              "+f"(acc[mt][nt][2]), "+f"(acc[mt][nt][3])
                            : "r"(af[mt][0]), "r"(af[mt][1]), "r"(af[mt][2]), "r"(af[mt][3]),
                              "r"(bfr[nt][0]), "r"(bfr[nt][1]));
            }
        }

        // epilogue: dist = x2 + e2 - 2*dot; float-only tile-min (pass2 re-derives
        // the exact argmin index by re-scanning candidate tiles in dist).
        {
            const int m0 = (tile & 255) * 128;
            const int n0 = bn * 128;
            const int cb = n0 + wn * 32 + 4 * qd;
            const float4 e2a = *(const float4*)(g_e2 + cb);
            const float4 e2b = *(const float4*)(g_e2 + cb + 16);
#pragma unroll
            for (int mt = 0; mt < 4; ++mt) {
#pragma unroll
                for (int h = 0; h < 2; ++h) {
                    int lrow = wm * 64 + mt * 16 + h * 8 + g;
                    int row = m0 + lrow;
                    float x2v = g_x2[row];
                    float4 va, vb;
                    va.x = fmaf(-2.f, acc[mt][0][h * 2 + 0], x2v + e2a.x);
                    va.y = fmaf(-2.f, acc[mt][0][h * 2 + 1], x2v + e2a.y);
                    va.z = fmaf(-2.f, acc[mt][1][h * 2 + 0], x2v + e2a.z);
                    va.w = fmaf(-2.f, acc[mt][1][h * 2 + 1], x2v + e2a.w);
                    vb.x = fmaf(-2.f, acc[mt][2][h * 2 + 0], x2v + e2b.x);
                    vb.y = fmaf(-2.f, acc[mt][2][h * 2 + 1], x2v + e2b.y);
                    vb.z = fmaf(-2.f, acc[mt][3][h * 2 + 0], x2v + e2b.z);
                    vb.w = fmaf(-2.f, acc[mt][3][h * 2 + 1], x2v + e2b.w);
                    float* dr = dist + (size_t)row * K_CODE + cb;
                    asm volatile("st.global.cs.v4.f32 [%0], {%1,%2,%3,%4};"
                                 :: "l"(dr), "f"(va.x), "f"(va.y), "f"(va.z), "f"(va.w)
                                 : "memory");
                    asm volatile("st.global.cs.v4.f32 [%0], {%1,%2,%3,%4};"
                                 :: "l"(dr + 16), "f"(vb.x), "f"(vb.y), "f"(vb.z), "f"(vb.w)
                                 : "memory");
                    float m8 = fminf(fminf(fminf(va.x, va.y), fminf(va.z, va.w)),
                                     fminf(fminf(vb.x, vb.y), fminf(vb.z, vb.w)));
                    m8 = fminf(m8, __shfl_xor_sync(0xffffffffu, m8, 1));
                    m8 = fminf(m8, __shfl_xor_sync(0xffffffffu, m8, 2));
                    if (qd == 0) sminf[lrow * 4 + wn] = m8;
                    // reset accumulators for next tile
#pragma unroll
                    for (int nt = 0; nt < 4; ++nt) {
                        acc[mt][nt][h * 2 + 0] = 0.f;
                        acc[mt][nt][h * 2 + 1] = 0.f;
                    }
                }
            }
            __syncthreads();   // sminf complete; also gates next iteration's fills
            if (tid < 128) {
                float m01 = fminf(sminf[tid * 4 + 0], sminf[tid * 4 + 1]);
                float m23 = fminf(sminf[tid * 4 + 2], sminf[tid * 4 + 3]);
                g_tbestf[(size_t)(m0 + tid) * NTILE + bn] = fminf(m01, m23);
            }
        }
    }
}

// ---- pass2: exact fp32 argmin fixup + quantized/indices/EMA scatter ----
__global__ void __launch_bounds__(256) pass2_kernel(
    const float* __restrict__ x, const float* __restrict__ embed,
    const float* __restrict__ dist, float* __restrict__ out_q, float* __restrict__ out_i) {
    const int lane = threadIdx.x & 31;
    const int row = blockIdx.x * 8 + (threadIdx.x >> 5);

    const float* tb = g_tbestf + (size_t)row * NTILE;
    float e0 = tb[lane], e1 = tb[lane + 32];
    float mn = fminf(e0, e1);
#pragma unroll
    for (int o = 16; o; o >>= 1) mn = fminf(mn, __shfl_xor_sync(0xffffffffu, mn, o));
    const float thr = mn + 2.0f;  // b* + 2*margin

    unsigned cand0 = __ballot_sync(0xffffffffu, e0 < thr);
    unsigned cand1 = __ballot_sync(0xffffffffu, e1 < thr);

    const float4 xl4 = *(const float4*)(x + (size_t)row * D_DIM + lane * 4);
    float bestv = 3.402823466e+38f;
    int bestc = 0x7fffffff;

#pragma unroll 1
    for (int grp = 0; grp < 2; ++grp) {
        unsigned cm = grp ? cand1 : cand0;
        while (cm) {
            int t = __ffs(cm) - 1;
            cm &= cm - 1;
            int tile = grp * 32 + t;
            float4 dv = *(const float4*)(dist + (size_t)row * K_CODE + tile * 128 + lane * 4);
            float dvv[4] = {dv.x, dv.y, dv.z, dv.w};
#pragma unroll
            for (int j = 0; j < 4; ++j) {
                unsigned mask = __ballot_sync(0xffffffffu, dvv[j] < thr);
                while (mask) {
                    int l = __ffs(mask) - 1;
                    mask &= mask - 1;
                    int col = tile * 128 + l * 4 + j;
                    float4 ev = *(const float4*)(embed + (size_t)col * D_DIM + lane * 4);
                    float d0 = xl4.x - ev.x, d1 = xl4.y - ev.y;
                    float d2 = xl4.z - ev.z, d3 = xl4.w - ev.w;
                    float s = d0 * d0 + d1 * d1 + d2 * d2 + d3 * d3;
#pragma unroll
                    for (int o = 16; o; o >>= 1) s += __shfl_xor_sync(0xffffffffu, s, o);
                    if (s < bestv || (s == bestv && col < bestc)) { bestv = s; bestc = col; }
                }
            }
        }
    }

    if (lane == 0) {
        out_i[row] = (float)bestc;
        atomicAdd(&g_cs[bestc], 1.0f);
    }
    float4 ev = *(const float4*)(embed + (size_t)bestc * D_DIM + lane * 4);
    *(float4*)(out_q + (size_t)row * D_DIM + lane * 4) = ev;
    float* esr = g_es + (size_t)bestc * D_DIM + lane * 4;
    atomicAdd(esr + 0, xl4.x);
    atomicAdd(esr + 1, xl4.y);
    atomicAdd(esr + 2, xl4.z);
    atomicAdd(esr + 3, xl4.w);
}

// multi-block: ncs write + global sum via atomics (g_S zeroed in prep)
__global__ void __launch_bounds__(256) finalA_kernel(const float* __restrict__ clus,
                                                     float* __restrict__ out_ncs) {
    int k = blockIdx.x * 256 + threadIdx.x;
    int lane = threadIdx.x & 31, wid = threadIdx.x >> 5;
    float v = DECAY * clus[k] + OMD * g_cs[k];
    out_ncs[k] = v;
    float s = v;
    for (int o = 16; o; o >>= 1) s += __shfl_xor_sync(0xffffffffu, s, o);
    __shared__ float sred[8];
    if (lane == 0) sred[wid] = s;
    __syncthreads();
    if (threadIdx.x == 0) {
        float b = sred[0] + sred[1] + sred[2] + sred[3]
                + sred[4] + sred[5] + sred[6] + sred[7];
        atomicAdd(&g_S, b);
    }
}

__global__ void finalB_kernel(const float* __restrict__ eavg, const float* __restrict__ clus,
                              float* __restrict__ out_nea, float* __restrict__ out_ne) {
    int i = blockIdx.x * blockDim.x + threadIdx.x;   // 0 .. K*D-1
    int k = i >> 7;
    float nea = DECAY * eavg[i] + OMD * g_es[i];
    out_nea[i] = nea;
    float ncs = DECAY * clus[k] + OMD * g_cs[k];
    float norm = (ncs + EPSF) / (g_S + (float)K_CODE * EPSF);
    out_ne[i] = nea / norm;
}

// ---------------- launch ----------------
extern "C" void kernel_launch(void* const* d_in, const int* in_sizes, int n_in,
                              void* d_out, int out_size) {
    (void)in_sizes; (void)n_in; (void)out_size;
    const float* x     = (const float*)d_in[0];
    const float* embed = (const float*)d_in[1];
    const float* clus  = (const float*)d_in[2];
    const float* eavg  = (const float*)d_in[3];
    float* out = (float*)d_out;

    float* out_q    = out;
    float* out_i    = out + OFF_I;
    float* out_dist = out + OFF_DIST;
    float* out_ne   = out + OFF_NE;
    float* out_ncs  = out + OFF_NCS;
    float* out_nea  = out + OFF_NEA;

    static int gemm_grid = 0;
    if (gemm_grid == 0) {
        cudaFuncSetAttribute(gemm_kernel, cudaFuncAttributeMaxDynamicSharedMemorySize,
                             GEMM_SMEM);
        int dev = 0, sms = 148;
        cudaGetDevice(&dev);
        cudaDeviceGetAttribute(&sms, cudaDevAttrMultiProcessorCount, dev);
        gemm_grid = 2 * sms;
    }

    prep_kernel<<<T_TOK / 8 + K_CODE / 8, 256>>>(x, embed);
    gemm_kernel<<<gemm_grid, 256, GEMM_SMEM>>>(out_dist, gemm_grid);
    pass2_kernel<<<T_TOK / 8, 256>>>(x, embed, out_dist, out_q, out_i);
    finalA_kernel<<<K_CODE / 256, 256>>>(clus, out_ncs);
    finalB_kernel<<<(K_CODE * D_DIM) / 256, 256>>>(eavg, clus, out_nea, out_ne);
}